// round 7
// baseline (speedup 1.0000x reference)
#include <cuda_runtime.h>
#include <cuda_bf16.h>
#include <math.h>
#include <stdint.h>

#define B_ 32
#define S_ 64
#define T_ 64
#define H_ 512
#define H3_ 1536
#define V_ 32000
#define NVT 250
#define ROWS 2048

typedef __nv_bfloat16 bf16;

// -------------------- device scratch --------------------
__device__ bf16 g_esrcbf[ROWS * H_];
__device__ float g_gxf[ROWS * H3_];
__device__ float g_gxb[ROWS * H3_];
__device__ bf16 g_srchidbf[ROWS * 1024];
__device__ bf16 g_Uhbf[ROWS * H_];
__device__ float g_henc[2][2][B_ * H_];
__device__ bf16  g_hencbf[2][2][B_ * H_];
__device__ float g_hdec[B_ * H_];
__device__ bf16  g_hdecbf[B_ * H_];
__device__ float g_O[B_ * 2048];          // [b][a(512) | ghr | ghz | ghn]
__device__ bf16 g_xembbf[ROWS * H_];      // all decoder input embeddings
__device__ float g_gxemb[ROWS * H3_];     // emb@Wih_e^T + bih, all steps
__device__ bf16 g_Pbf[ROWS * H3_];        // SH@Wih_c^T
__device__ bf16 g_decbf[ROWS * H_];
__device__ bf16 g_Wihf_bf[H3_ * H_];
__device__ bf16 g_Wihb_bf[H3_ * H_];
__device__ bf16 g_Whhf_bf[H3_ * H_];
__device__ bf16 g_Whhb_bf[H3_ * H_];
__device__ bf16 g_Uw_bf[H_ * 1024];
__device__ bf16 g_AW_bf[H_ * H_];
__device__ bf16 g_dWih_bf[H3_ * H3_];
__device__ bf16 g_dWhh_bf[H3_ * H_];
__device__ bf16 g_Wbf[V_ * H_];
__device__ float g_partial[ROWS * NVT];
__device__ float g_picked[ROWS];
__device__ float g_rowloss[ROWS];
__device__ float g_rowvalid[ROWS];
__device__ float g_zbias[H3_];
__device__ unsigned g_cnt, g_gen;

__device__ __forceinline__ float sigf(float x) { return 1.f / (1.f + __expf(-x)); }
__device__ __forceinline__ float tanha(float x) {
    float y; asm("tanh.approx.f32 %0,%1;" : "=f"(y) : "f"(x)); return y;
}

__device__ __forceinline__ void gridbar(int nblk) {
    __threadfence();
    __syncthreads();
    if (threadIdx.x == 0) {
        unsigned my = atomicAdd(&g_gen, 0u);
        if (atomicAdd(&g_cnt, 1u) == (unsigned)(nblk - 1)) {
            atomicExch(&g_cnt, 0u);
            __threadfence();
            atomicExch(&g_gen, my + 1u);
        } else {
            while (atomicAdd(&g_gen, 0u) == my) {}
        }
        __threadfence();
    }
    __syncthreads();
}

__device__ __forceinline__ uint32_t cvsm(const void* p) {
    return (uint32_t)__cvta_generic_to_shared(p);
}
__device__ __forceinline__ void ldm_x4(uint32_t* r, uint32_t a) {
    asm volatile("ldmatrix.sync.aligned.m8n8.x4.shared.b16 {%0,%1,%2,%3},[%4];\n"
                 : "=r"(r[0]), "=r"(r[1]), "=r"(r[2]), "=r"(r[3]) : "r"(a));
}
__device__ __forceinline__ void ldm_x2(uint32_t* r, uint32_t a) {
    asm volatile("ldmatrix.sync.aligned.m8n8.x2.shared.b16 {%0,%1},[%2];\n"
                 : "=r"(r[0]), "=r"(r[1]) : "r"(a));
}
__device__ __forceinline__ void mma16816(float* d, const uint32_t* a, const uint32_t* b) {
    asm volatile("mma.sync.aligned.m16n8k16.row.col.f32.bf16.bf16.f32 "
                 "{%0,%1,%2,%3},{%4,%5,%6,%7},{%8,%9},{%0,%1,%2,%3};\n"
                 : "+f"(d[0]), "+f"(d[1]), "+f"(d[2]), "+f"(d[3])
                 : "r"(a[0]), "r"(a[1]), "r"(a[2]), "r"(a[3]), "r"(b[0]), "r"(b[1]));
}
__device__ __forceinline__ void cpa16(uint32_t dst, const void* src) {
    asm volatile("cp.async.cg.shared.global [%0], [%1], 16;\n" :: "r"(dst), "l"(src));
}

// -------------------- init / embeds --------------------
__global__ void init_states() {
    int i = blockIdx.x * 256 + threadIdx.x;
    if (i < B_ * H_) {
        g_henc[0][0][i] = 0.f; g_henc[1][0][i] = 0.f;
        g_hencbf[0][0][i] = __float2bfloat16(0.f);
        g_hencbf[1][0][i] = __float2bfloat16(0.f);
        g_hdec[i] = 0.f;
        g_hdecbf[i] = __float2bfloat16(0.f);
    }
    if (i < H3_) g_zbias[i] = 0.f;
    if (i == 0) { g_cnt = 0u; g_gen = 0u; }
}

__global__ void embed_src(const int* __restrict__ seqs, const float* __restrict__ emb) {
    int i = blockIdx.x * 256 + threadIdx.x;
    int bs = i >> 9, j = i & 511;
    g_esrcbf[i] = __float2bfloat16(emb[seqs[bs] * H_ + j]);
}
__global__ void embed_tgt(const int* __restrict__ seqs, const float* __restrict__ emb) {
    int i = blockIdx.x * 256 + threadIdx.x;
    int bs = i >> 9, j = i & 511;
    g_xembbf[i] = __float2bfloat16(emb[seqs[bs] * H_ + j]);
}

// -------------------- fused weight conversion (9 segments) --------------------
#define C0 786432
#define C1 1572864
#define C2 2359296
#define C3 3145728
#define C4 3670016
#define C5 3932160
#define C6 6291456
#define C7 7077888
#define C8 23461888
__global__ void conv_all(const float* w0, const float* w1, const float* w2,
                         const float* w3, const float* w4, const float* w5,
                         const float* w6, const float* w7, const float* w8) {
    long long e = (long long)(blockIdx.x * 256 + threadIdx.x) * 4;
    const float* src; bf16* dst; long long off;
    if      (e < C0) { src = w0; dst = g_Wihf_bf; off = 0; }
    else if (e < C1) { src = w1; dst = g_Wihb_bf; off = C0; }
    else if (e < C2) { src = w2; dst = g_Whhf_bf; off = C1; }
    else if (e < C3) { src = w3; dst = g_Whhb_bf; off = C2; }
    else if (e < C4) { src = w4; dst = g_Uw_bf;   off = C3; }
    else if (e < C5) { src = w5; dst = g_AW_bf;   off = C4; }
    else if (e < C6) { src = w6; dst = g_dWih_bf; off = C5; }
    else if (e < C7) { src = w7; dst = g_dWhh_bf; off = C6; }
    else             { src = w8; dst = g_Wbf;     off = C7; }
    long long i = e - off;
    float4 v = *(const float4*)&src[i];
    dst[i] = __float2bfloat16(v.x);
    dst[i + 1] = __float2bfloat16(v.y);
    dst[i + 2] = __float2bfloat16(v.z);
    dst[i + 3] = __float2bfloat16(v.w);
}

// -------------------- flexible bf16 mma GEMM: C[2048, ncols] = A@W^T + bias --------------------
template<int OUT_BF>
__global__ __launch_bounds__(256) void mma_gemm(const bf16* __restrict__ A, int lda,
                                                const bf16* __restrict__ W0,
                                                const bf16* __restrict__ W1,
                                                int ldw, int kwoff,
                                                const float* __restrict__ bias0,
                                                const float* __restrict__ bias1,
                                                float* __restrict__ Cf0, float* __restrict__ Cf1,
                                                bf16* __restrict__ Cb, int ldc, int K) {
    __shared__ bf16 As[128][40];
    __shared__ bf16 Bs[128][40];
    const bf16* W = blockIdx.z ? W1 : W0;
    const float* bias = blockIdx.z ? bias1 : bias0;
    float* Cf = blockIdx.z ? Cf1 : Cf0;
    int tid = threadIdx.x, lane = tid & 31, wid = tid >> 5;
    int wm = wid & 3, wn = wid >> 2;
    int row0 = blockIdx.y * 128, col0 = blockIdx.x * 128;
    float acc[2][8][4];
#pragma unroll
    for (int mt = 0; mt < 2; mt++)
#pragma unroll
        for (int nt = 0; nt < 8; nt++)
#pragma unroll
            for (int c = 0; c < 4; c++) acc[mt][nt][c] = 0.f;

    for (int k0 = 0; k0 < K; k0 += 32) {
        int r = tid >> 2, c = tid & 3;
        *(uint4*)&As[r][c * 8] = *(const uint4*)&A[(row0 + r) * lda + k0 + c * 8];
        *(uint4*)&As[r + 64][c * 8] = *(const uint4*)&A[(row0 + r + 64) * lda + k0 + c * 8];
        *(uint4*)&Bs[r][c * 8] = *(const uint4*)&W[(col0 + r) * ldw + kwoff + k0 + c * 8];
        *(uint4*)&Bs[r + 64][c * 8] = *(const uint4*)&W[(col0 + r + 64) * ldw + kwoff + k0 + c * 8];
        __syncthreads();
#pragma unroll
        for (int kk = 0; kk < 2; kk++) {
            int kb = kk * 16;
            uint32_t af[2][4];
#pragma unroll
            for (int mt = 0; mt < 2; mt++)
                ldm_x4(af[mt], cvsm(&As[wm * 32 + mt * 16 + (lane & 15)][kb + ((lane & 16) ? 8 : 0)]));
            uint32_t bfr[8][2];
#pragma unroll
            for (int np = 0; np < 4; np++) {
                uint32_t t4[4];
                ldm_x4(t4, cvsm(&Bs[wn * 64 + np * 16 + (lane & 7) + ((lane & 16) ? 8 : 0)][kb + ((lane & 8) ? 8 : 0)]));
                bfr[np * 2][0] = t4[0]; bfr[np * 2][1] = t4[1];
                bfr[np * 2 + 1][0] = t4[2]; bfr[np * 2 + 1][1] = t4[3];
            }
#pragma unroll
            for (int mt = 0; mt < 2; mt++)
#pragma unroll
                for (int nt = 0; nt < 8; nt++)
                    mma16816(acc[mt][nt], af[mt], bfr[nt]);
        }
        __syncthreads();
    }
#pragma unroll
    for (int mt = 0; mt < 2; mt++)
#pragma unroll
        for (int nt = 0; nt < 8; nt++) {
            int cb = col0 + wn * 64 + nt * 8 + (lane & 3) * 2;
            float b0 = bias[cb], b1 = bias[cb + 1];
#pragma unroll
            for (int h = 0; h < 2; h++) {
                int row = row0 + wm * 32 + mt * 16 + (lane >> 2) + h * 8;
                float v0 = acc[mt][nt][h * 2] + b0;
                float v1 = acc[mt][nt][h * 2 + 1] + b1;
                if (OUT_BF) {
                    Cb[row * ldc + cb] = __float2bfloat16(v0);
                    Cb[row * ldc + cb + 1] = __float2bfloat16(v1);
                } else {
                    Cf[row * ldc + cb] = v0;
                    Cf[row * ldc + cb + 1] = v1;
                }
            }
        }
}

// -------------------- persistent encoder (unchanged from R6: 1 barrier/step) --------------------
__global__ __launch_bounds__(128) void enc_persist(const float* __restrict__ bhh_f,
                                                   const float* __restrict__ bhh_b,
                                                   const int* __restrict__ slen) {
    extern __shared__ char smem[];
    bf16 (*Wsm)[520] = (bf16(*)[520])smem;
    bf16 (*Hsm)[520] = (bf16(*)[520])(smem + 24 * 520 * 2);
    int bid = blockIdx.x, tid = threadIdx.x, lane = tid & 31, w = tid >> 5;
    int dir = bid >> 6, jt = bid & 63;
    const bf16* Wg = dir ? g_Whhb_bf : g_Whhf_bf;
    const float* bhh = dir ? bhh_b : bhh_f;
    const float* gx = dir ? g_gxb : g_gxf;

    for (int i = tid; i < 24 * 64; i += 128) {
        int r = i >> 6, ch = i & 63;
        int grow = (r >> 3) * 512 + jt * 8 + (r & 7);
        *(uint4*)&Wsm[r][ch * 8] = *(const uint4*)&Wg[grow * 512 + ch * 8];
    }

    for (int t = 0; t < S_; t++) {
        int rd = t & 1, wr = rd ^ 1;
        for (int i = tid; i < 32 * 64; i += 128) {
            int r = i >> 6, ch = i & 63;
            *(uint4*)&Hsm[r][ch * 8] = *(const uint4*)&g_hencbf[dir][rd][r * 512 + ch * 8];
        }
        __syncthreads();
        if (w < 2) {
            float acc[3][4] = {{0.f,0.f,0.f,0.f},{0.f,0.f,0.f,0.f},{0.f,0.f,0.f,0.f}};
#pragma unroll 4
            for (int ks = 0; ks < 32; ks++) {
                uint32_t a4[4];
                ldm_x4(a4, cvsm(&Hsm[16 * w + (lane & 15)][ks * 16 + ((lane & 16) ? 8 : 0)]));
#pragma unroll
                for (int g = 0; g < 3; g++) {
                    uint32_t b2[2];
                    ldm_x2(b2, cvsm(&Wsm[g * 8 + (lane & 7)][ks * 16 + ((lane & 8) ? 8 : 0)]));
                    mma16816(acc[g], a4, b2);
                }
            }
            int tf = dir ? (63 - t) : t;
            int r0 = 16 * w + (lane >> 2);
            int c0 = jt * 8 + (lane & 3) * 2;
#pragma unroll
            for (int hh = 0; hh < 2; hh++) {
                int b = r0 + hh * 8;
                bool m = tf < slen[b];
                int base = (b * 64 + tf) * 1536;
#pragma unroll
                for (int cc = 0; cc < 2; cc++) {
                    int j = c0 + cc;
                    int ai = hh * 2 + cc;
                    float ghr = acc[0][ai] + bhh[j];
                    float ghz = acc[1][ai] + bhh[512 + j];
                    float ghn = acc[2][ai] + bhh[1024 + j];
                    float h = g_henc[dir][rd][b * 512 + j];
                    float r = sigf(gx[base + j] + ghr);
                    float z = sigf(gx[base + 512 + j] + ghz);
                    float n = tanhf(gx[base + 1024 + j] + r * ghn);
                    float hn = (1.f - z) * n + z * h;
                    float hout = m ? hn : h;
                    g_henc[dir][wr][b * 512 + j] = hout;
                    g_hencbf[dir][wr][b * 512 + j] = __float2bfloat16(hout);
                    g_srchidbf[(b * 64 + tf) * 1024 + dir * 512 + j] = __float2bfloat16(m ? hn : 0.f);
                }
            }
        }
        gridbar(128);
    }
}

// -------------------- persistent decoder: 96 blocks, 2 barriers/step --------------------
// blocks 0..31  : attention+pointwise (one batch each)
// blocks 32..95 : h-GEMM, 32 cols each of Ocomb[2048] = [A_W | Whh(3 gates)]
__global__ __launch_bounds__(256) void dec_persist(const float* __restrict__ Ab,
                                                   const float* __restrict__ Av,
                                                   const float* __restrict__ dbhh,
                                                   const int* __restrict__ slen,
                                                   const int* __restrict__ tlen) {
    extern __shared__ char smem[];
    int bid = blockIdx.x, tid = threadIdx.x, lane = tid & 31, w = tid >> 5;

    if (bid < 32) {
        int b = bid;
        bf16 (*Uhc)[520] = (bf16(*)[520])smem;                      // 64 rows
        float* a_sm = (float*)(smem + 64 * 520 * 2);                // 512
        float* gxs = a_sm + 512;                                    // 1536
        float* wts = gxs + 1536;                                    // 64
        for (int i = tid; i < 64 * 64; i += 256) {
            int s = i >> 6, ch = i & 63;
            *(uint4*)&Uhc[s][ch * 8] = *(const uint4*)&g_Uhbf[(b * 64 + s) * 512 + ch * 8];
        }
        int L = slen[b];
        int TL = tlen[b];
        for (int t = 0; t < T_; t++) {
            gridbar(96);            // after h-GEMM (stage A)
            // ---- attention ----
            for (int j = tid; j < 512; j += 256) a_sm[j] = g_O[b * 2048 + j];
            __syncthreads();
#pragma unroll
            for (int si = 0; si < 8; si++) {
                int s = w * 8 + si;
                float p = 0.f;
#pragma unroll 4
                for (int j = lane; j < 512; j += 32)
                    p += Av[j] * tanha(__bfloat162float(Uhc[s][j]) + a_sm[j]);
#pragma unroll
                for (int o = 16; o > 0; o >>= 1) p += __shfl_xor_sync(0xffffffffu, p, o);
                if (lane == 0) wts[s] = (s < L) ? p : p - 1e9f;
            }
            __syncthreads();
            if (w == 0) {
                float e0 = wts[lane], e1 = wts[lane + 32];
                float m = fmaxf(e0, e1);
#pragma unroll
                for (int o = 16; o > 0; o >>= 1) m = fmaxf(m, __shfl_xor_sync(0xffffffffu, m, o));
                float x0 = __expf(e0 - m), x1 = __expf(e1 - m);
                float sm = x0 + x1;
#pragma unroll
                for (int o = 16; o > 0; o >>= 1) sm += __shfl_xor_sync(0xffffffffu, sm, o);
                float inv = 1.f / sm;
                wts[lane] = x0 * inv;
                wts[lane + 32] = x1 * inv;
            }
            __syncthreads();
            // ---- gx = gxemb(precomputed, has dbih) + sum_s w_s * P[b,s,:] ----
            {
                const float* ge = g_gxemb + (b * 64 + t) * 1536;
#pragma unroll 1
                for (int jj = tid; jj < 768; jj += 256) {
                    int j = jj * 2;
                    float s0 = ge[j], s1 = ge[j + 1];
                    const __nv_bfloat162* Pp = (const __nv_bfloat162*)(g_Pbf + (b * 64) * 1536 + j);
#pragma unroll 16
                    for (int ss = 0; ss < 64; ss++) {
                        float2 pv = __bfloat1622float2(Pp[ss * 768]);
                        s0 += wts[ss] * pv.x;
                        s1 += wts[ss] * pv.y;
                    }
                    gxs[j] = s0; gxs[j + 1] = s1;
                }
            }
            __syncthreads();
            // ---- GRU pointwise for row b ----
            bool m = t < TL;
            for (int j = tid; j < 512; j += 256) {
                float gxr = gxs[j], gxz = gxs[512 + j], gxn = gxs[1024 + j];
                float ghr = g_O[b * 2048 + 512 + j];
                float ghz = g_O[b * 2048 + 1024 + j];
                float ghn = g_O[b * 2048 + 1536 + j];
                float h = g_hdec[b * 512 + j];
                float r = sigf(gxr + ghr);
                float z = sigf(gxz + ghz);
                float n = tanhf(gxn + r * ghn);
                float hn = (1.f - z) * n + z * h;
                float hout = m ? hn : h;
                g_hdec[b * 512 + j] = hout;
                g_hdecbf[b * 512 + j] = __float2bfloat16(hout);
                g_decbf[(b * 64 + t) * 512 + j] = __float2bfloat16(m ? hn : 0.f);
            }
            gridbar(96);            // h' visible to next stage A
        }
    } else {
        int gid = bid - 32;
        int gc0 = gid * 32;
        bf16 (*Wsm)[520] = (bf16(*)[520])smem;                      // 32 rows
        bf16 (*Hsm)[520] = (bf16(*)[520])(smem + 32 * 520 * 2);     // 32 rows
        const bf16* Wsrc = (gc0 < 512) ? (g_AW_bf + gc0 * 512) : (g_dWhh_bf + (gc0 - 512) * 512);
        for (int i = tid; i < 32 * 64; i += 256) {
            int r = i >> 6, ch = i & 63;
            *(uint4*)&Wsm[r][ch * 8] = *(const uint4*)&Wsrc[r * 512 + ch * 8];
        }
        int wm = w >> 2, wn = w & 3;   // 8 warps: 2 m-tiles x 4 n8-groups
        for (int t = 0; t < T_; t++) {
            // ---- stage A: Ocomb = h @ [A_W|Whh]^T + [Ab|dbhh] ----
            for (int i = tid; i < 32 * 64; i += 256) {
                int r = i >> 6, ch = i & 63;
                *(uint4*)&Hsm[r][ch * 8] = *(const uint4*)&g_hdecbf[r * 512 + ch * 8];
            }
            __syncthreads();
            float acc[4] = {0.f, 0.f, 0.f, 0.f};
#pragma unroll 4
            for (int ks = 0; ks < 32; ks++) {
                uint32_t a4[4], b2[2];
                ldm_x4(a4, cvsm(&Hsm[wm * 16 + (lane & 15)][ks * 16 + ((lane & 16) ? 8 : 0)]));
                ldm_x2(b2, cvsm(&Wsm[wn * 8 + (lane & 7)][ks * 16 + ((lane & 8) ? 8 : 0)]));
                mma16816(acc, a4, b2);
            }
            {
                int c0 = gc0 + wn * 8 + (lane & 3) * 2;
                float b0 = (c0 < 512) ? Ab[c0] : dbhh[c0 - 512];
                float b1 = (c0 + 1 < 512) ? Ab[c0 + 1] : dbhh[c0 + 1 - 512];
                int r0 = wm * 16 + (lane >> 2);
                g_O[r0 * 2048 + c0] = acc[0] + b0;
                g_O[r0 * 2048 + c0 + 1] = acc[1] + b1;
                g_O[(r0 + 8) * 2048 + c0] = acc[2] + b0;
                g_O[(r0 + 8) * 2048 + c0 + 1] = acc[3] + b1;
            }
            gridbar(96);
            // stage B: idle (attention blocks work)
            gridbar(96);
            __syncthreads();
        }
    }
}

// -------------------- logits GEMM (cp.async 2-stage) + exp-sum + pick --------------------
__global__ __launch_bounds__(256) void logits_mma(const float* __restrict__ bias,
                                                  const int* __restrict__ tseq) {
    __shared__ bf16 As[2][128][40];
    __shared__ bf16 Bs[2][128][40];
    __shared__ float rowsum[128][2];
    int tid = threadIdx.x, lane = tid & 31, wid = tid >> 5;
    int wm = wid & 3, wn = wid >> 2;
    int row0 = blockIdx.y * 128, col0 = blockIdx.x * 128;
    int r = tid >> 2, c = tid & 3;
    float acc[2][8][4];
#pragma unroll
    for (int mt = 0; mt < 2; mt++)
#pragma unroll
        for (int nt = 0; nt < 8; nt++)
#pragma unroll
            for (int cc = 0; cc < 4; cc++) acc[mt][nt][cc] = 0.f;

#define ISSUE(kt, st)                                                                  \
    do {                                                                               \
        int k0_ = (kt) * 32;                                                           \
        cpa16(cvsm(&As[st][r][c * 8]), &g_decbf[(row0 + r) * 512 + k0_ + c * 8]);      \
        cpa16(cvsm(&As[st][r + 64][c * 8]), &g_decbf[(row0 + r + 64) * 512 + k0_ + c * 8]); \
        cpa16(cvsm(&Bs[st][r][c * 8]), &g_Wbf[(col0 + r) * 512 + k0_ + c * 8]);        \
        cpa16(cvsm(&Bs[st][r + 64][c * 8]), &g_Wbf[(col0 + r + 64) * 512 + k0_ + c * 8]); \
        asm volatile("cp.async.commit_group;");                                        \
    } while (0)

    ISSUE(0, 0);
    for (int kt = 0; kt < 16; kt++) {
        int st = kt & 1;
        if (kt < 15) {
            ISSUE(kt + 1, st ^ 1);
            asm volatile("cp.async.wait_group 1;");
        } else {
            asm volatile("cp.async.wait_group 0;");
        }
        __syncthreads();
#pragma unroll
        for (int kk = 0; kk < 2; kk++) {
            int kb = kk * 16;
            uint32_t af[2][4];
#pragma unroll
            for (int mt = 0; mt < 2; mt++)
                ldm_x4(af[mt], cvsm(&As[st][wm * 32 + mt * 16 + (lane & 15)][kb + ((lane & 16) ? 8 : 0)]));
            uint32_t bfr[8][2];
#pragma unroll
            for (int np = 0; np < 4; np++) {
                uint32_t t4[4];
                ldm_x4(t4, cvsm(&Bs[st][wn * 64 + np * 16 + (lane & 7) + ((lane & 16) ? 8 : 0)][kb + ((lane & 8) ? 8 : 0)]));
                bfr[np * 2][0] = t4[0]; bfr[np * 2][1] = t4[1];
                bfr[np * 2 + 1][0] = t4[2]; bfr[np * 2 + 1][1] = t4[3];
            }
#pragma unroll
            for (int mt = 0; mt < 2; mt++)
#pragma unroll
                for (int nt = 0; nt < 8; nt++)
                    mma16816(acc[mt][nt], af[mt], bfr[nt]);
        }
        __syncthreads();
    }
#undef ISSUE

    float sums[2][2] = {{0.f, 0.f}, {0.f, 0.f}};
    int gl[2][2];
#pragma unroll
    for (int mt = 0; mt < 2; mt++)
#pragma unroll
        for (int h = 0; h < 2; h++) {
            int row = row0 + wm * 32 + mt * 16 + (lane >> 2) + h * 8;
            int tt = row & 63;
            gl[mt][h] = (tt < T_ - 1) ? tseq[(row >> 6) * T_ + tt + 1] : 0;
        }
#pragma unroll
    for (int mt = 0; mt < 2; mt++)
#pragma unroll
        for (int nt = 0; nt < 8; nt++) {
            int cb = col0 + wn * 64 + nt * 8 + (lane & 3) * 2;
            float b0 = bias[cb], b1 = bias[cb + 1];
#pragma unroll
            for (int h = 0; h < 2; h++) {
                float v0 = acc[mt][nt][h * 2] + b0;
                float v1 = acc[mt][nt][h * 2 + 1] + b1;
                sums[mt][h] += __expf(v0) + __expf(v1);
                int row = row0 + wm * 32 + mt * 16 + (lane >> 2) + h * 8;
                if (cb == gl[mt][h]) g_picked[row] = v0;
                if (cb + 1 == gl[mt][h]) g_picked[row] = v1;
            }
        }
#pragma unroll
    for (int mt = 0; mt < 2; mt++)
#pragma unroll
        for (int h = 0; h < 2; h++) {
            float s = sums[mt][h];
            s += __shfl_xor_sync(0xffffffffu, s, 1);
            s += __shfl_xor_sync(0xffffffffu, s, 2);
            if ((lane & 3) == 0)
                rowsum[wm * 32 + mt * 16 + (lane >> 2) + h * 8][wn] = s;
        }
    __syncthreads();
    if (tid < 128)
        g_partial[(row0 + tid) * NVT + blockIdx.x] = rowsum[tid][0] + rowsum[tid][1];
}

__global__ void rowloss_kernel(const int* __restrict__ tseq) {
    int r = blockIdx.x, tid = threadIdx.x;
    float s = 0.f;
    for (int v = tid; v < NVT; v += 128) s += g_partial[r * NVT + v];
#pragma unroll
    for (int o = 16; o > 0; o >>= 1) s += __shfl_xor_sync(0xffffffffu, s, o);
    __shared__ float w[4];
    if ((tid & 31) == 0) w[tid >> 5] = s;
    __syncthreads();
    if (tid == 0) {
        float sum = w[0] + w[1] + w[2] + w[3];
        int b = r >> 6, t = r & 63;
        int g = (t < T_ - 1) ? tseq[b * T_ + t + 1] : 0;
        if (g != 0) { g_rowloss[r] = logf(sum) - g_picked[r]; g_rowvalid[r] = 1.f; }
        else        { g_rowloss[r] = 0.f;                     g_rowvalid[r] = 0.f; }
    }
}

__global__ void final_kernel(float* __restrict__ out) {
    int tid = threadIdx.x;
    float s = 0.f, c = 0.f;
    for (int r = tid; r < ROWS; r += 256) { s += g_rowloss[r]; c += g_rowvalid[r]; }
#pragma unroll
    for (int o = 16; o > 0; o >>= 1) {
        s += __shfl_xor_sync(0xffffffffu, s, o);
        c += __shfl_xor_sync(0xffffffffu, c, o);
    }
    __shared__ float ws[8], wc[8];
    if ((tid & 31) == 0) { ws[tid >> 5] = s; wc[tid >> 5] = c; }
    __syncthreads();
    if (tid == 0) {
        float S = 0.f, C = 0.f;
        for (int i = 0; i < 8; i++) { S += ws[i]; C += wc[i]; }
        out[0] = S / C;
    }
}

// -------------------- launch --------------------
extern "C" void kernel_launch(void* const* d_in, const int* in_sizes, int n_in,
                              void* d_out, int out_size) {
    const int*   src_seqs = (const int*)d_in[0];
    const int*   src_len  = (const int*)d_in[1];
    const int*   tgt_seqs = (const int*)d_in[2];
    const int*   tgt_len  = (const int*)d_in[3];
    const float* src_emb  = (const float*)d_in[4];
    const float* eWih_f   = (const float*)d_in[5];
    const float* eWhh_f   = (const float*)d_in[6];
    const float* ebih_f   = (const float*)d_in[7];
    const float* ebhh_f   = (const float*)d_in[8];
    const float* eWih_b   = (const float*)d_in[9];
    const float* eWhh_b   = (const float*)d_in[10];
    const float* ebih_b   = (const float*)d_in[11];
    const float* ebhh_b   = (const float*)d_in[12];
    const float* tgt_emb  = (const float*)d_in[13];
    const float* dWih     = (const float*)d_in[14];
    const float* dWhh     = (const float*)d_in[15];
    const float* dbih     = (const float*)d_in[16];
    const float* dbhh     = (const float*)d_in[17];
    const float* U_w      = (const float*)d_in[18];
    const float* U_b      = (const float*)d_in[19];
    const float* A_W      = (const float*)d_in[20];
    const float* A_b      = (const float*)d_in[21];
    const float* A_v      = (const float*)d_in[22];
    const float* out_w    = (const float*)d_in[23];
    const float* out_b    = (const float*)d_in[24];

    bf16 *wihf, *wihb, *uw, *dwih, *esrc, *srchid, *uhbf, *pbf, *xemb;
    float *gxf, *gxb, *gxe, *zb;
    cudaGetSymbolAddress((void**)&wihf, g_Wihf_bf);
    cudaGetSymbolAddress((void**)&wihb, g_Wihb_bf);
    cudaGetSymbolAddress((void**)&uw, g_Uw_bf);
    cudaGetSymbolAddress((void**)&dwih, g_dWih_bf);
    cudaGetSymbolAddress((void**)&esrc, g_esrcbf);
    cudaGetSymbolAddress((void**)&srchid, g_srchidbf);
    cudaGetSymbolAddress((void**)&uhbf, g_Uhbf);
    cudaGetSymbolAddress((void**)&pbf, g_Pbf);
    cudaGetSymbolAddress((void**)&xemb, g_xembbf);
    cudaGetSymbolAddress((void**)&gxf, g_gxf);
    cudaGetSymbolAddress((void**)&gxb, g_gxb);
    cudaGetSymbolAddress((void**)&gxe, g_gxemb);
    cudaGetSymbolAddress((void**)&zb, g_zbias);

    cudaFuncSetAttribute(enc_persist, cudaFuncAttributeMaxDynamicSharedMemorySize, 58240);
    cudaFuncSetAttribute(dec_persist, cudaFuncAttributeMaxDynamicSharedMemorySize, 76800);

    init_states<<<64, 256>>>();
    embed_src<<<4096, 256>>>(src_seqs, src_emb);
    embed_tgt<<<4096, 256>>>(tgt_seqs, tgt_emb);
    conv_all<<<22912, 256>>>(eWih_f, eWih_b, eWhh_f, eWhh_b, U_w, A_W, dWih, dWhh, out_w);

    // encoder input gates (both dirs)
    mma_gemm<0><<<dim3(12, 16, 2), 256>>>(esrc, H_, wihf, wihb, H_, 0,
                                          ebih_f, ebih_b, gxf, gxb, (bf16*)0, H3_, H_);
    // decoder embedding gate-input (precompute, includes dbih)
    mma_gemm<0><<<dim3(12, 16, 1), 256>>>(xemb, H_, dwih, dwih, H3_, 0,
                                          dbih, dbih, gxe, gxe, (bf16*)0, H3_, H_);

    enc_persist<<<128, 128, 58240>>>(ebhh_f, ebhh_b, src_len);

    // Uh = srchid @ U_w^T + U_b (bf16)
    mma_gemm<1><<<dim3(4, 16, 1), 256>>>(srchid, 1024, uw, uw, 1024, 0,
                                         U_b, U_b, (float*)0, (float*)0, uhbf, H_, 1024);
    // P = srchid @ Wih_c^T (bf16, no bias)
    mma_gemm<1><<<dim3(12, 16, 1), 256>>>(srchid, 1024, dwih, dwih, H3_, 512,
                                          zb, zb, (float*)0, (float*)0, pbf, H3_, 1024);

    dec_persist<<<96, 256, 76800>>>(A_b, A_v, dbhh, src_len, tgt_len);

    logits_mma<<<dim3(NVT, 16), 256>>>(out_b, tgt_seqs);
    rowloss_kernel<<<ROWS, 128>>>(tgt_seqs);
    final_kernel<<<1, 256>>>((float*)d_out);
}

// round 8
// speedup vs baseline: 1.3820x; 1.3820x over previous
#include <cuda_runtime.h>
#include <cuda_bf16.h>
#include <math.h>
#include <stdint.h>

#define B_ 32
#define S_ 64
#define T_ 64
#define H_ 512
#define H3_ 1536
#define V_ 32000
#define NVT 250
#define ROWS 2048

typedef __nv_bfloat16 bf16;

// -------------------- device scratch --------------------
__device__ bf16 g_esrcbf[ROWS * H_];
__device__ float g_gxf[ROWS * H3_];
__device__ float g_gxb[ROWS * H3_];
__device__ bf16 g_srchidbf[ROWS * 1024];
__device__ bf16 g_Uhbf[ROWS * H_];
__device__ float g_henc[2][2][B_ * H_];
__device__ bf16  g_hencbf[2][2][B_ * H_];
__device__ float g_hdec[B_ * H_];
__device__ bf16  g_hdecbf[B_ * H_];
__device__ float g_a[B_ * H_];
__device__ bf16 g_xembbf[ROWS * H_];
__device__ float g_gxemb[ROWS * H3_];     // emb@Wih_e^T + dbih for every (b,t)
__device__ bf16 g_cbf[B_ * 1024];
__device__ bf16 g_decbf[ROWS * H_];
__device__ bf16 g_Wihf_bf[H3_ * H_];
__device__ bf16 g_Wihb_bf[H3_ * H_];
__device__ bf16 g_Whhf_bf[H3_ * H_];
__device__ bf16 g_Whhb_bf[H3_ * H_];
__device__ bf16 g_Uw_bf[H_ * 1024];
__device__ bf16 g_AW_bf[H_ * H_];
__device__ bf16 g_dWih_bf[H3_ * H3_];
__device__ bf16 g_dWhh_bf[H3_ * H_];
__device__ bf16 g_Wbf[V_ * H_];
__device__ float g_partial[ROWS * NVT];
__device__ float g_picked[ROWS];
__device__ float g_rowloss[ROWS];
__device__ float g_rowvalid[ROWS];
__device__ unsigned g_cnt, g_gen;

__device__ __forceinline__ float sigf(float x) { return 1.f / (1.f + __expf(-x)); }
__device__ __forceinline__ float tanha(float x) {
    float y; asm("tanh.approx.f32 %0,%1;" : "=f"(y) : "f"(x)); return y;
}

__device__ __forceinline__ void gridbar(int nblk) {
    __threadfence();
    __syncthreads();
    if (threadIdx.x == 0) {
        unsigned my = atomicAdd(&g_gen, 0u);
        if (atomicAdd(&g_cnt, 1u) == (unsigned)(nblk - 1)) {
            atomicExch(&g_cnt, 0u);
            __threadfence();
            atomicExch(&g_gen, my + 1u);
        } else {
            while (atomicAdd(&g_gen, 0u) == my) {}
        }
        __threadfence();
    }
    __syncthreads();
}

__device__ __forceinline__ uint32_t cvsm(const void* p) {
    return (uint32_t)__cvta_generic_to_shared(p);
}
__device__ __forceinline__ void ldm_x4(uint32_t* r, uint32_t a) {
    asm volatile("ldmatrix.sync.aligned.m8n8.x4.shared.b16 {%0,%1,%2,%3},[%4];\n"
                 : "=r"(r[0]), "=r"(r[1]), "=r"(r[2]), "=r"(r[3]) : "r"(a));
}
__device__ __forceinline__ void ldm_x2(uint32_t* r, uint32_t a) {
    asm volatile("ldmatrix.sync.aligned.m8n8.x2.shared.b16 {%0,%1},[%2];\n"
                 : "=r"(r[0]), "=r"(r[1]) : "r"(a));
}
__device__ __forceinline__ void mma16816(float* d, const uint32_t* a, const uint32_t* b) {
    asm volatile("mma.sync.aligned.m16n8k16.row.col.f32.bf16.bf16.f32 "
                 "{%0,%1,%2,%3},{%4,%5,%6,%7},{%8,%9},{%0,%1,%2,%3};\n"
                 : "+f"(d[0]), "+f"(d[1]), "+f"(d[2]), "+f"(d[3])
                 : "r"(a[0]), "r"(a[1]), "r"(a[2]), "r"(a[3]), "r"(b[0]), "r"(b[1]));
}
__device__ __forceinline__ void cpa16(uint32_t dst, const void* src) {
    asm volatile("cp.async.cg.shared.global [%0], [%1], 16;\n" :: "r"(dst), "l"(src));
}

// -------------------- init / embeds --------------------
__global__ void init_states() {
    int i = blockIdx.x * 256 + threadIdx.x;
    if (i < B_ * H_) {
        g_henc[0][0][i] = 0.f; g_henc[1][0][i] = 0.f;
        g_hencbf[0][0][i] = __float2bfloat16(0.f);
        g_hencbf[1][0][i] = __float2bfloat16(0.f);
        g_hdec[i] = 0.f;
        g_hdecbf[i] = __float2bfloat16(0.f);
    }
    if (i == 0) { g_cnt = 0u; g_gen = 0u; }
}

__global__ void embed_src(const int* __restrict__ seqs, const float* __restrict__ emb) {
    int i = blockIdx.x * 256 + threadIdx.x;
    int bs = i >> 9, j = i & 511;
    g_esrcbf[i] = __float2bfloat16(emb[seqs[bs] * H_ + j]);
}
__global__ void embed_tgt(const int* __restrict__ seqs, const float* __restrict__ emb) {
    int i = blockIdx.x * 256 + threadIdx.x;
    int bs = i >> 9, j = i & 511;
    g_xembbf[i] = __float2bfloat16(emb[seqs[bs] * H_ + j]);
}

// -------------------- fused weight conversion --------------------
#define C0 786432
#define C1 1572864
#define C2 2359296
#define C3 3145728
#define C4 3670016
#define C5 3932160
#define C6 6291456
#define C7 7077888
__global__ void conv_all(const float* w0, const float* w1, const float* w2,
                         const float* w3, const float* w4, const float* w5,
                         const float* w6, const float* w7, const float* w8) {
    long long e = (long long)(blockIdx.x * 256 + threadIdx.x) * 4;
    const float* src; bf16* dst; long long off;
    if      (e < C0) { src = w0; dst = g_Wihf_bf; off = 0; }
    else if (e < C1) { src = w1; dst = g_Wihb_bf; off = C0; }
    else if (e < C2) { src = w2; dst = g_Whhf_bf; off = C1; }
    else if (e < C3) { src = w3; dst = g_Whhb_bf; off = C2; }
    else if (e < C4) { src = w4; dst = g_Uw_bf;   off = C3; }
    else if (e < C5) { src = w5; dst = g_AW_bf;   off = C4; }
    else if (e < C6) { src = w6; dst = g_dWih_bf; off = C5; }
    else if (e < C7) { src = w7; dst = g_dWhh_bf; off = C6; }
    else             { src = w8; dst = g_Wbf;     off = C7; }
    long long i = e - off;
    float4 v = *(const float4*)&src[i];
    dst[i] = __float2bfloat16(v.x);
    dst[i + 1] = __float2bfloat16(v.y);
    dst[i + 2] = __float2bfloat16(v.z);
    dst[i + 3] = __float2bfloat16(v.w);
}

// -------------------- flexible bf16 mma GEMM: C[2048, ...] = A@W^T + bias --------------------
template<int OUT_BF>
__global__ __launch_bounds__(256) void mma_gemm(const bf16* __restrict__ A, int lda,
                                                const bf16* __restrict__ W0,
                                                const bf16* __restrict__ W1,
                                                int ldw, int kwoff,
                                                const float* __restrict__ bias0,
                                                const float* __restrict__ bias1,
                                                float* __restrict__ Cf0, float* __restrict__ Cf1,
                                                bf16* __restrict__ Cb, int ldc, int K) {
    __shared__ bf16 As[128][40];
    __shared__ bf16 Bs[128][40];
    const bf16* W = blockIdx.z ? W1 : W0;
    const float* bias = blockIdx.z ? bias1 : bias0;
    float* Cf = blockIdx.z ? Cf1 : Cf0;
    int tid = threadIdx.x, lane = tid & 31, wid = tid >> 5;
    int wm = wid & 3, wn = wid >> 2;
    int row0 = blockIdx.y * 128, col0 = blockIdx.x * 128;
    float acc[2][8][4];
#pragma unroll
    for (int mt = 0; mt < 2; mt++)
#pragma unroll
        for (int nt = 0; nt < 8; nt++)
#pragma unroll
            for (int c = 0; c < 4; c++) acc[mt][nt][c] = 0.f;

    for (int k0 = 0; k0 < K; k0 += 32) {
        int r = tid >> 2, c = tid & 3;
        *(uint4*)&As[r][c * 8] = *(const uint4*)&A[(row0 + r) * lda + k0 + c * 8];
        *(uint4*)&As[r + 64][c * 8] = *(const uint4*)&A[(row0 + r + 64) * lda + k0 + c * 8];
        *(uint4*)&Bs[r][c * 8] = *(const uint4*)&W[(col0 + r) * ldw + kwoff + k0 + c * 8];
        *(uint4*)&Bs[r + 64][c * 8] = *(const uint4*)&W[(col0 + r + 64) * ldw + kwoff + k0 + c * 8];
        __syncthreads();
#pragma unroll
        for (int kk = 0; kk < 2; kk++) {
            int kb = kk * 16;
            uint32_t af[2][4];
#pragma unroll
            for (int mt = 0; mt < 2; mt++)
                ldm_x4(af[mt], cvsm(&As[wm * 32 + mt * 16 + (lane & 15)][kb + ((lane & 16) ? 8 : 0)]));
            uint32_t bfr[8][2];
#pragma unroll
            for (int np = 0; np < 4; np++) {
                uint32_t t4[4];
                ldm_x4(t4, cvsm(&Bs[wn * 64 + np * 16 + (lane & 7) + ((lane & 16) ? 8 : 0)][kb + ((lane & 8) ? 8 : 0)]));
                bfr[np * 2][0] = t4[0]; bfr[np * 2][1] = t4[1];
                bfr[np * 2 + 1][0] = t4[2]; bfr[np * 2 + 1][1] = t4[3];
            }
#pragma unroll
            for (int mt = 0; mt < 2; mt++)
#pragma unroll
                for (int nt = 0; nt < 8; nt++)
                    mma16816(acc[mt][nt], af[mt], bfr[nt]);
        }
        __syncthreads();
    }
#pragma unroll
    for (int mt = 0; mt < 2; mt++)
#pragma unroll
        for (int nt = 0; nt < 8; nt++) {
            int cb = col0 + wn * 64 + nt * 8 + (lane & 3) * 2;
            float b0 = bias[cb], b1 = bias[cb + 1];
#pragma unroll
            for (int h = 0; h < 2; h++) {
                int row = row0 + wm * 32 + mt * 16 + (lane >> 2) + h * 8;
                float v0 = acc[mt][nt][h * 2] + b0;
                float v1 = acc[mt][nt][h * 2 + 1] + b1;
                if (OUT_BF) {
                    Cb[row * ldc + cb] = __float2bfloat16(v0);
                    Cb[row * ldc + cb + 1] = __float2bfloat16(v1);
                } else {
                    Cf[row * ldc + cb] = v0;
                    Cf[row * ldc + cb + 1] = v1;
                }
            }
        }
}

// -------------------- persistent encoder: 128 blocks, 1 barrier/step --------------------
__global__ __launch_bounds__(128) void enc_persist(const float* __restrict__ bhh_f,
                                                   const float* __restrict__ bhh_b,
                                                   const int* __restrict__ slen) {
    extern __shared__ char smem[];
    bf16 (*Wsm)[520] = (bf16(*)[520])smem;
    bf16 (*Hsm)[520] = (bf16(*)[520])(smem + 24 * 520 * 2);
    int bid = blockIdx.x, tid = threadIdx.x, lane = tid & 31, w = tid >> 5;
    int dir = bid >> 6, jt = bid & 63;
    const bf16* Wg = dir ? g_Whhb_bf : g_Whhf_bf;
    const float* bhh = dir ? bhh_b : bhh_f;
    const float* gx = dir ? g_gxb : g_gxf;

    for (int i = tid; i < 24 * 64; i += 128) {
        int r = i >> 6, ch = i & 63;
        int grow = (r >> 3) * 512 + jt * 8 + (r & 7);
        *(uint4*)&Wsm[r][ch * 8] = *(const uint4*)&Wg[grow * 512 + ch * 8];
    }

    for (int t = 0; t < S_; t++) {
        int rd = t & 1, wr = rd ^ 1;
        for (int i = tid; i < 32 * 64; i += 128) {
            int r = i >> 6, ch = i & 63;
            *(uint4*)&Hsm[r][ch * 8] = *(const uint4*)&g_hencbf[dir][rd][r * 512 + ch * 8];
        }
        __syncthreads();
        if (w < 2) {
            float acc[3][4] = {{0.f,0.f,0.f,0.f},{0.f,0.f,0.f,0.f},{0.f,0.f,0.f,0.f}};
#pragma unroll 4
            for (int ks = 0; ks < 32; ks++) {
                uint32_t a4[4];
                ldm_x4(a4, cvsm(&Hsm[16 * w + (lane & 15)][ks * 16 + ((lane & 16) ? 8 : 0)]));
#pragma unroll
                for (int g = 0; g < 3; g++) {
                    uint32_t b2[2];
                    ldm_x2(b2, cvsm(&Wsm[g * 8 + (lane & 7)][ks * 16 + ((lane & 8) ? 8 : 0)]));
                    mma16816(acc[g], a4, b2);
                }
            }
            int tf = dir ? (63 - t) : t;
            int r0 = 16 * w + (lane >> 2);
            int c0 = jt * 8 + (lane & 3) * 2;
#pragma unroll
            for (int hh = 0; hh < 2; hh++) {
                int b = r0 + hh * 8;
                bool m = tf < slen[b];
                int base = (b * 64 + tf) * 1536;
#pragma unroll
                for (int cc = 0; cc < 2; cc++) {
                    int j = c0 + cc;
                    int ai = hh * 2 + cc;
                    float ghr = acc[0][ai] + bhh[j];
                    float ghz = acc[1][ai] + bhh[512 + j];
                    float ghn = acc[2][ai] + bhh[1024 + j];
                    float h = g_henc[dir][rd][b * 512 + j];
                    float r = sigf(gx[base + j] + ghr);
                    float z = sigf(gx[base + 512 + j] + ghz);
                    float n = tanhf(gx[base + 1024 + j] + r * ghn);
                    float hn = (1.f - z) * n + z * h;
                    float hout = m ? hn : h;
                    g_henc[dir][wr][b * 512 + j] = hout;
                    g_hencbf[dir][wr][b * 512 + j] = __float2bfloat16(hout);
                    g_srchidbf[(b * 64 + tf) * 1024 + dir * 512 + j] = __float2bfloat16(m ? hn : 0.f);
                }
            }
        }
        gridbar(128);
    }
}

// -------------------- persistent decoder: 96 blocks, 3 barriers/step --------------------
// blocks 0..31  : attention (one batch each): energies+softmax+context
// blocks 32..95 : gemm blocks (j-slice of 8 cols): a+gh GEMM, then ctx GEMM + pointwise
__global__ __launch_bounds__(256) void dec_persist(const float* __restrict__ Ab,
                                                   const float* __restrict__ Av,
                                                   const float* __restrict__ dbhh,
                                                   const int* __restrict__ slen,
                                                   const int* __restrict__ tlen) {
    extern __shared__ char smem[];
    int bid = blockIdx.x, tid = threadIdx.x, lane = tid & 31, w = tid >> 5;

    if (bid < 32) {
        int b = bid;
        bf16 (*Uhc)[520] = (bf16(*)[520])smem;                          // 64 rows
        bf16 (*SHc)[1048] = (bf16(*)[1048])(smem + 64 * 520 * 2);       // 64 rows
        float* a_sm = (float*)(smem + 64 * 520 * 2 + 64 * 1048 * 2);    // 512
        float* wts = a_sm + 512;                                        // 64
        for (int i = tid; i < 64 * 64; i += 256) {
            int s = i >> 6, ch = i & 63;
            *(uint4*)&Uhc[s][ch * 8] = *(const uint4*)&g_Uhbf[(b * 64 + s) * 512 + ch * 8];
        }
        for (int i = tid; i < 64 * 128; i += 256) {
            int s = i >> 7, ch = i & 127;
            *(uint4*)&SHc[s][ch * 8] = *(const uint4*)&g_srchidbf[(b * 64 + s) * 1024 + ch * 8];
        }
        int L = slen[b];
        for (int t = 0; t < T_; t++) {
            gridbar(96);    // stage A done: g_a ready
            for (int j = tid; j < 512; j += 256) a_sm[j] = g_a[b * 512 + j] + Ab[j];
            __syncthreads();
#pragma unroll
            for (int si = 0; si < 8; si++) {
                int s = w * 8 + si;
                float p = 0.f;
#pragma unroll 4
                for (int j = lane; j < 512; j += 32)
                    p += Av[j] * tanha(__bfloat162float(Uhc[s][j]) + a_sm[j]);
#pragma unroll
                for (int o = 16; o > 0; o >>= 1) p += __shfl_xor_sync(0xffffffffu, p, o);
                if (lane == 0) wts[s] = (s < L) ? p : p - 1e9f;
            }
            __syncthreads();
            if (w == 0) {
                float e0 = wts[lane], e1 = wts[lane + 32];
                float m = fmaxf(e0, e1);
#pragma unroll
                for (int o = 16; o > 0; o >>= 1) m = fmaxf(m, __shfl_xor_sync(0xffffffffu, m, o));
                float x0 = __expf(e0 - m), x1 = __expf(e1 - m);
                float sm = x0 + x1;
#pragma unroll
                for (int o = 16; o > 0; o >>= 1) sm += __shfl_xor_sync(0xffffffffu, sm, o);
                float inv = 1.f / sm;
                wts[lane] = x0 * inv;
                wts[lane + 32] = x1 * inv;
            }
            __syncthreads();
            for (int j = tid; j < 1024; j += 256) {
                float c0 = 0.f, c1 = 0.f;
#pragma unroll 16
                for (int s = 0; s < 64; s += 2) {
                    c0 += wts[s] * __bfloat162float(SHc[s][j]);
                    c1 += wts[s + 1] * __bfloat162float(SHc[s + 1][j]);
                }
                g_cbf[b * 1024 + j] = __float2bfloat16(c0 + c1);
            }
            gridbar(96);    // c ready
            gridbar(96);    // pointwise done (h ready for next step)
        }
    } else {
        int gid = bid - 32;
        bf16 (*Wih)[1032] = (bf16(*)[1032])smem;                                  // 24 rows (ctx cols)
        bf16 (*Whh)[520] = (bf16(*)[520])(smem + 24 * 1032 * 2);                  // 24 rows
        bf16 (*AWc)[520] = (bf16(*)[520])(smem + 24 * 1032 * 2 + 24 * 520 * 2);   // 8 rows
        bf16 (*Asm)[1048] = (bf16(*)[1048])(smem + 24 * 1032 * 2 + 32 * 520 * 2); // 32 rows
        for (int i = tid; i < 24 * 128; i += 256) {
            int r = i >> 7, ch = i & 127;
            int grow = (r >> 3) * 512 + gid * 8 + (r & 7);
            *(uint4*)&Wih[r][ch * 8] = *(const uint4*)&g_dWih_bf[grow * 1536 + 512 + ch * 8];
        }
        for (int i = tid; i < 24 * 64; i += 256) {
            int r = i >> 6, ch = i & 63;
            int grow = (r >> 3) * 512 + gid * 8 + (r & 7);
            *(uint4*)&Whh[r][ch * 8] = *(const uint4*)&g_dWhh_bf[grow * 512 + ch * 8];
        }
        for (int i = tid; i < 8 * 64; i += 256) {
            int r = i >> 6, ch = i & 63;
            *(uint4*)&AWc[r][ch * 8] = *(const uint4*)&g_AW_bf[(gid * 8 + r) * 512 + ch * 8];
        }
        for (int t = 0; t < T_; t++) {
            float acch[3][4] = {{0.f,0.f,0.f,0.f},{0.f,0.f,0.f,0.f},{0.f,0.f,0.f,0.f}};
            // ---- stage A: a = h@A_W^T, gh = h@Whh^T ----
            for (int i = tid; i < 32 * 64; i += 256) {
                int r = i >> 6, ch = i & 63;
                *(uint4*)&Asm[r][ch * 8] = *(const uint4*)&g_hdecbf[r * 512 + ch * 8];
            }
            __syncthreads();
            if (w < 2) {
                float acca[4] = {0.f, 0.f, 0.f, 0.f};
#pragma unroll 4
                for (int ks = 0; ks < 32; ks++) {
                    uint32_t a4[4];
                    ldm_x4(a4, cvsm(&Asm[16 * w + (lane & 15)][ks * 16 + ((lane & 16) ? 8 : 0)]));
                    uint32_t b2[2];
                    ldm_x2(b2, cvsm(&AWc[(lane & 7)][ks * 16 + ((lane & 8) ? 8 : 0)]));
                    mma16816(acca, a4, b2);
#pragma unroll
                    for (int g = 0; g < 3; g++) {
                        uint32_t bh[2];
                        ldm_x2(bh, cvsm(&Whh[g * 8 + (lane & 7)][ks * 16 + ((lane & 8) ? 8 : 0)]));
                        mma16816(acch[g], a4, bh);
                    }
                }
                int r0 = 16 * w + (lane >> 2);
                int c0 = gid * 8 + (lane & 3) * 2;
                g_a[r0 * 512 + c0] = acca[0];
                g_a[r0 * 512 + c0 + 1] = acca[1];
                g_a[(r0 + 8) * 512 + c0] = acca[2];
                g_a[(r0 + 8) * 512 + c0 + 1] = acca[3];
            }
            gridbar(96);    // a ready; attention runs
            gridbar(96);    // c ready
            // ---- stage C: gx_ctx = c@Wih_c^T ; pointwise with gxemb ----
            for (int i = tid; i < 32 * 128; i += 256) {
                int r = i >> 7, ch = i & 127;
                *(uint4*)&Asm[r][ch * 8] = *(const uint4*)&g_cbf[r * 1024 + ch * 8];
            }
            __syncthreads();
            if (w < 2) {
                float accx[3][4] = {{0.f,0.f,0.f,0.f},{0.f,0.f,0.f,0.f},{0.f,0.f,0.f,0.f}};
#pragma unroll 4
                for (int ks = 0; ks < 64; ks++) {
                    uint32_t a4[4];
                    ldm_x4(a4, cvsm(&Asm[16 * w + (lane & 15)][ks * 16 + ((lane & 16) ? 8 : 0)]));
#pragma unroll
                    for (int g = 0; g < 3; g++) {
                        uint32_t b2[2];
                        ldm_x2(b2, cvsm(&Wih[g * 8 + (lane & 7)][ks * 16 + ((lane & 8) ? 8 : 0)]));
                        mma16816(accx[g], a4, b2);
                    }
                }
                int r0 = 16 * w + (lane >> 2);
                int c0 = gid * 8 + (lane & 3) * 2;
#pragma unroll
                for (int hh = 0; hh < 2; hh++) {
                    int b = r0 + hh * 8;
                    bool m = t < tlen[b];
                    const float* ge = g_gxemb + (b * 64 + t) * 1536;
#pragma unroll
                    for (int cc = 0; cc < 2; cc++) {
                        int j = c0 + cc;
                        int ai = hh * 2 + cc;
                        float gxr = accx[0][ai] + ge[j];
                        float gxz = accx[1][ai] + ge[512 + j];
                        float gxn = accx[2][ai] + ge[1024 + j];
                        float ghr = acch[0][ai] + dbhh[j];
                        float ghz = acch[1][ai] + dbhh[512 + j];
                        float ghn = acch[2][ai] + dbhh[1024 + j];
                        float h = g_hdec[b * 512 + j];
                        float r = sigf(gxr + ghr);
                        float z = sigf(gxz + ghz);
                        float n = tanhf(gxn + r * ghn);
                        float hn = (1.f - z) * n + z * h;
                        float hout = m ? hn : h;
                        g_hdec[b * 512 + j] = hout;
                        g_hdecbf[b * 512 + j] = __float2bfloat16(hout);
                        g_decbf[(b * 64 + t) * 512 + j] = __float2bfloat16(m ? hn : 0.f);
                    }
                }
            }
            gridbar(96);    // h ready for next step
        }
    }
}

// -------------------- logits GEMM (cp.async 2-stage) + exp-sum + pick --------------------
__global__ __launch_bounds__(256) void logits_mma(const float* __restrict__ bias,
                                                  const int* __restrict__ tseq) {
    __shared__ bf16 As[2][128][40];
    __shared__ bf16 Bs[2][128][40];
    __shared__ float rowsum[128][2];
    int tid = threadIdx.x, lane = tid & 31, wid = tid >> 5;
    int wm = wid & 3, wn = wid >> 2;
    int row0 = blockIdx.y * 128, col0 = blockIdx.x * 128;
    int r = tid >> 2, c = tid & 3;
    float acc[2][8][4];
#pragma unroll
    for (int mt = 0; mt < 2; mt++)
#pragma unroll
        for (int nt = 0; nt < 8; nt++)
#pragma unroll
            for (int cc = 0; cc < 4; cc++) acc[mt][nt][cc] = 0.f;

#define ISSUE(kt, st)                                                                  \
    do {                                                                               \
        int k0_ = (kt) * 32;                                                           \
        cpa16(cvsm(&As[st][r][c * 8]), &g_decbf[(row0 + r) * 512 + k0_ + c * 8]);      \
        cpa16(cvsm(&As[st][r + 64][c * 8]), &g_decbf[(row0 + r + 64) * 512 + k0_ + c * 8]); \
        cpa16(cvsm(&Bs[st][r][c * 8]), &g_Wbf[(col0 + r) * 512 + k0_ + c * 8]);        \
        cpa16(cvsm(&Bs[st][r + 64][c * 8]), &g_Wbf[(col0 + r + 64) * 512 + k0_ + c * 8]); \
        asm volatile("cp.async.commit_group;");                                        \
    } while (0)

    ISSUE(0, 0);
    for (int kt = 0; kt < 16; kt++) {
        int st = kt & 1;
        if (kt < 15) {
            ISSUE(kt + 1, st ^ 1);
            asm volatile("cp.async.wait_group 1;");
        } else {
            asm volatile("cp.async.wait_group 0;");
        }
        __syncthreads();
#pragma unroll
        for (int kk = 0; kk < 2; kk++) {
            int kb = kk * 16;
            uint32_t af[2][4];
#pragma unroll
            for (int mt = 0; mt < 2; mt++)
                ldm_x4(af[mt], cvsm(&As[st][wm * 32 + mt * 16 + (lane & 15)][kb + ((lane & 16) ? 8 : 0)]));
            uint32_t bfr[8][2];
#pragma unroll
            for (int np = 0; np < 4; np++) {
                uint32_t t4[4];
                ldm_x4(t4, cvsm(&Bs[st][wn * 64 + np * 16 + (lane & 7) + ((lane & 16) ? 8 : 0)][kb + ((lane & 8) ? 8 : 0)]));
                bfr[np * 2][0] = t4[0]; bfr[np * 2][1] = t4[1];
                bfr[np * 2 + 1][0] = t4[2]; bfr[np * 2 + 1][1] = t4[3];
            }
#pragma unroll
            for (int mt = 0; mt < 2; mt++)
#pragma unroll
                for (int nt = 0; nt < 8; nt++)
                    mma16816(acc[mt][nt], af[mt], bfr[nt]);
        }
        __syncthreads();
    }
#undef ISSUE

    float sums[2][2] = {{0.f, 0.f}, {0.f, 0.f}};
    int gl[2][2];
#pragma unroll
    for (int mt = 0; mt < 2; mt++)
#pragma unroll
        for (int h = 0; h < 2; h++) {
            int row = row0 + wm * 32 + mt * 16 + (lane >> 2) + h * 8;
            int tt = row & 63;
            gl[mt][h] = (tt < T_ - 1) ? tseq[(row >> 6) * T_ + tt + 1] : 0;
        }
#pragma unroll
    for (int mt = 0; mt < 2; mt++)
#pragma unroll
        for (int nt = 0; nt < 8; nt++) {
            int cb = col0 + wn * 64 + nt * 8 + (lane & 3) * 2;
            float b0 = bias[cb], b1 = bias[cb + 1];
#pragma unroll
            for (int h = 0; h < 2; h++) {
                float v0 = acc[mt][nt][h * 2] + b0;
                float v1 = acc[mt][nt][h * 2 + 1] + b1;
                sums[mt][h] += __expf(v0) + __expf(v1);
                int row = row0 + wm * 32 + mt * 16 + (lane >> 2) + h * 8;
                if (cb == gl[mt][h]) g_picked[row] = v0;
                if (cb + 1 == gl[mt][h]) g_picked[row] = v1;
            }
        }
#pragma unroll
    for (int mt = 0; mt < 2; mt++)
#pragma unroll
        for (int h = 0; h < 2; h++) {
            float s = sums[mt][h];
            s += __shfl_xor_sync(0xffffffffu, s, 1);
            s += __shfl_xor_sync(0xffffffffu, s, 2);
            if ((lane & 3) == 0)
                rowsum[wm * 32 + mt * 16 + (lane >> 2) + h * 8][wn] = s;
        }
    __syncthreads();
    if (tid < 128)
        g_partial[(row0 + tid) * NVT + blockIdx.x] = rowsum[tid][0] + rowsum[tid][1];
}

__global__ void rowloss_kernel(const int* __restrict__ tseq) {
    int r = blockIdx.x, tid = threadIdx.x;
    float s = 0.f;
    for (int v = tid; v < NVT; v += 128) s += g_partial[r * NVT + v];
#pragma unroll
    for (int o = 16; o > 0; o >>= 1) s += __shfl_xor_sync(0xffffffffu, s, o);
    __shared__ float w[4];
    if ((tid & 31) == 0) w[tid >> 5] = s;
    __syncthreads();
    if (tid == 0) {
        float sum = w[0] + w[1] + w[2] + w[3];
        int b = r >> 6, t = r & 63;
        int g = (t < T_ - 1) ? tseq[b * T_ + t + 1] : 0;
        if (g != 0) { g_rowloss[r] = logf(sum) - g_picked[r]; g_rowvalid[r] = 1.f; }
        else        { g_rowloss[r] = 0.f;                     g_rowvalid[r] = 0.f; }
    }
}

__global__ void final_kernel(float* __restrict__ out) {
    int tid = threadIdx.x;
    float s = 0.f, c = 0.f;
    for (int r = tid; r < ROWS; r += 256) { s += g_rowloss[r]; c += g_rowvalid[r]; }
#pragma unroll
    for (int o = 16; o > 0; o >>= 1) {
        s += __shfl_xor_sync(0xffffffffu, s, o);
        c += __shfl_xor_sync(0xffffffffu, c, o);
    }
    __shared__ float ws[8], wc[8];
    if ((tid & 31) == 0) { ws[tid >> 5] = s; wc[tid >> 5] = c; }
    __syncthreads();
    if (tid == 0) {
        float S = 0.f, C = 0.f;
        for (int i = 0; i < 8; i++) { S += ws[i]; C += wc[i]; }
        out[0] = S / C;
    }
}

// -------------------- launch --------------------
extern "C" void kernel_launch(void* const* d_in, const int* in_sizes, int n_in,
                              void* d_out, int out_size) {
    const int*   src_seqs = (const int*)d_in[0];
    const int*   src_len  = (const int*)d_in[1];
    const int*   tgt_seqs = (const int*)d_in[2];
    const int*   tgt_len  = (const int*)d_in[3];
    const float* src_emb  = (const float*)d_in[4];
    const float* eWih_f   = (const float*)d_in[5];
    const float* eWhh_f   = (const float*)d_in[6];
    const float* ebih_f   = (const float*)d_in[7];
    const float* ebhh_f   = (const float*)d_in[8];
    const float* eWih_b   = (const float*)d_in[9];
    const float* eWhh_b   = (const float*)d_in[10];
    const float* ebih_b   = (const float*)d_in[11];
    const float* ebhh_b   = (const float*)d_in[12];
    const float* tgt_emb  = (const float*)d_in[13];
    const float* dWih     = (const float*)d_in[14];
    const float* dWhh     = (const float*)d_in[15];
    const float* dbih     = (const float*)d_in[16];
    const float* dbhh     = (const float*)d_in[17];
    const float* U_w      = (const float*)d_in[18];
    const float* U_b      = (const float*)d_in[19];
    const float* A_W      = (const float*)d_in[20];
    const float* A_b      = (const float*)d_in[21];
    const float* A_v      = (const float*)d_in[22];
    const float* out_w    = (const float*)d_in[23];
    const float* out_b    = (const float*)d_in[24];

    bf16 *wihf, *wihb, *uw, *dwih, *esrc, *srchid, *uhbf, *xemb;
    float *gxf, *gxb, *gxe;
    cudaGetSymbolAddress((void**)&wihf, g_Wihf_bf);
    cudaGetSymbolAddress((void**)&wihb, g_Wihb_bf);
    cudaGetSymbolAddress((void**)&uw, g_Uw_bf);
    cudaGetSymbolAddress((void**)&dwih, g_dWih_bf);
    cudaGetSymbolAddress((void**)&esrc, g_esrcbf);
    cudaGetSymbolAddress((void**)&srchid, g_srchidbf);
    cudaGetSymbolAddress((void**)&uhbf, g_Uhbf);
    cudaGetSymbolAddress((void**)&xemb, g_xembbf);
    cudaGetSymbolAddress((void**)&gxf, g_gxf);
    cudaGetSymbolAddress((void**)&gxb, g_gxb);
    cudaGetSymbolAddress((void**)&gxe, g_gxemb);

    cudaFuncSetAttribute(enc_persist, cudaFuncAttributeMaxDynamicSharedMemorySize, 58240);
    cudaFuncSetAttribute(dec_persist, cudaFuncAttributeMaxDynamicSharedMemorySize, 203008);

    init_states<<<64, 256>>>();
    embed_src<<<4096, 256>>>(src_seqs, src_emb);
    embed_tgt<<<4096, 256>>>(tgt_seqs, tgt_emb);
    conv_all<<<22912, 256>>>(eWih_f, eWih_b, eWhh_f, eWhh_b, U_w, A_W, dWih, dWhh, out_w);

    // encoder input gates (both dirs)
    mma_gemm<0><<<dim3(12, 16, 2), 256>>>(esrc, H_, wihf, wihb, H_, 0,
                                          ebih_f, ebih_b, gxf, gxb, (bf16*)0, H3_, H_);
    // decoder embedding gate-input precompute (includes dbih)
    mma_gemm<0><<<dim3(12, 16, 1), 256>>>(xemb, H_, dwih, dwih, H3_, 0,
                                          dbih, dbih, gxe, gxe, (bf16*)0, H3_, H_);

    enc_persist<<<128, 128, 58240>>>(ebhh_f, ebhh_b, src_len);

    // Uh = srchid @ U_w^T + U_b (bf16 out)
    mma_gemm<1><<<dim3(4, 16, 1), 256>>>(srchid, 1024, uw, uw, 1024, 0,
                                         U_b, U_b, (float*)0, (float*)0, uhbf, H_, 1024);

    dec_persist<<<96, 256, 203008>>>(A_b, A_v, dbhh, src_len, tgt_len);

    logits_mma<<<dim3(NVT, 16), 256>>>(out_b, tgt_seqs);
    rowloss_kernel<<<ROWS, 128>>>(tgt_seqs);
    final_kernel<<<1, 256>>>((float*)d_out);
}

// round 9
// speedup vs baseline: 1.8764x; 1.3578x over previous
#include <cuda_runtime.h>
#include <cuda_bf16.h>
#include <math.h>
#include <stdint.h>

#define B_ 32
#define S_ 64
#define T_ 64
#define H_ 512
#define H3_ 1536
#define V_ 32000
#define NVT 250
#define ROWS 2048

typedef __nv_bfloat16 bf16;

// -------------------- device scratch --------------------
__device__ bf16 g_esrcbf[ROWS * H_];
__device__ float g_gxf[ROWS * H3_];
__device__ float g_gxb[ROWS * H3_];
__device__ bf16 g_srchidbf[ROWS * 1024];
__device__ bf16 g_Uhbf[ROWS * H_];
__device__ float g_henc[2][2][B_ * H_];
__device__ bf16  g_hencbf[2][2][B_ * H_];
__device__ float g_hdec[B_ * H_];
__device__ bf16  g_hdecbf[B_ * H_];
__device__ float g_a[B_ * H_];
__device__ bf16 g_xembbf[ROWS * H_];
__device__ float g_gxemb[ROWS * H3_];     // emb@Wih_e^T + dbih for every (b,t)
__device__ bf16 g_cbf[B_ * 1024];
__device__ bf16 g_decbf[ROWS * H_];
__device__ bf16 g_Wihf_bf[H3_ * H_];
__device__ bf16 g_Wihb_bf[H3_ * H_];
__device__ bf16 g_Whhf_bf[H3_ * H_];
__device__ bf16 g_Whhb_bf[H3_ * H_];
__device__ bf16 g_Uw_bf[H_ * 1024];
__device__ bf16 g_AW_bf[H_ * H_];
__device__ bf16 g_dWih_bf[H3_ * H3_];
__device__ bf16 g_dWhh_bf[H3_ * H_];
__device__ bf16 g_Wbf[V_ * H_];
__device__ float g_partial[ROWS * NVT];
__device__ float g_picked[ROWS];
__device__ float g_rowloss[ROWS];
__device__ float g_rowvalid[ROWS];
__device__ unsigned g_semA, g_semB, g_semC, g_semE;

__device__ __forceinline__ float sigf(float x) { return 1.f / (1.f + __expf(-x)); }
__device__ __forceinline__ float tanha(float x) {
    float y; asm("tanh.approx.f32 %0,%1;" : "=f"(y) : "f"(x)); return y;
}

// -------------------- monotonic semaphores --------------------
__device__ __forceinline__ void sem_signal(unsigned* s) {
    asm volatile("red.release.gpu.global.add.u32 [%0],1;" :: "l"(s) : "memory");
}
__device__ __forceinline__ void sem_spin(unsigned* s, unsigned target) {
    unsigned v;
    do { asm volatile("ld.acquire.gpu.global.u32 %0,[%1];" : "=r"(v) : "l"(s) : "memory"); }
    while (v < target);
}
// arrive: all block threads' writes globally visible, then count once
__device__ __forceinline__ void sem_arrive_block(unsigned* s) {
    __threadfence();
    __syncthreads();
    if (threadIdx.x == 0) sem_signal(s);
}
__device__ __forceinline__ void sem_wait_block(unsigned* s, unsigned target) {
    if (threadIdx.x == 0) sem_spin(s, target);
    __syncthreads();
}

__device__ __forceinline__ uint32_t cvsm(const void* p) {
    return (uint32_t)__cvta_generic_to_shared(p);
}
__device__ __forceinline__ void ldm_x4(uint32_t* r, uint32_t a) {
    asm volatile("ldmatrix.sync.aligned.m8n8.x4.shared.b16 {%0,%1,%2,%3},[%4];\n"
                 : "=r"(r[0]), "=r"(r[1]), "=r"(r[2]), "=r"(r[3]) : "r"(a));
}
__device__ __forceinline__ void ldm_x2(uint32_t* r, uint32_t a) {
    asm volatile("ldmatrix.sync.aligned.m8n8.x2.shared.b16 {%0,%1},[%2];\n"
                 : "=r"(r[0]), "=r"(r[1]) : "r"(a));
}
__device__ __forceinline__ void mma16816(float* d, const uint32_t* a, const uint32_t* b) {
    asm volatile("mma.sync.aligned.m16n8k16.row.col.f32.bf16.bf16.f32 "
                 "{%0,%1,%2,%3},{%4,%5,%6,%7},{%8,%9},{%0,%1,%2,%3};\n"
                 : "+f"(d[0]), "+f"(d[1]), "+f"(d[2]), "+f"(d[3])
                 : "r"(a[0]), "r"(a[1]), "r"(a[2]), "r"(a[3]), "r"(b[0]), "r"(b[1]));
}
__device__ __forceinline__ void cpa16(uint32_t dst, const void* src) {
    asm volatile("cp.async.cg.shared.global [%0], [%1], 16;\n" :: "r"(dst), "l"(src));
}

// -------------------- init / embeds --------------------
__global__ void init_states() {
    int i = blockIdx.x * 256 + threadIdx.x;
    if (i < B_ * H_) {
        g_henc[0][0][i] = 0.f; g_henc[1][0][i] = 0.f;
        g_hencbf[0][0][i] = __float2bfloat16(0.f);
        g_hencbf[1][0][i] = __float2bfloat16(0.f);
        g_hdec[i] = 0.f;
        g_hdecbf[i] = __float2bfloat16(0.f);
    }
    if (i == 0) { g_semA = 0u; g_semB = 0u; g_semC = 0u; g_semE = 0u; }
}

__global__ void embed_src(const int* __restrict__ seqs, const float* __restrict__ emb) {
    int i = blockIdx.x * 256 + threadIdx.x;
    int bs = i >> 9, j = i & 511;
    g_esrcbf[i] = __float2bfloat16(emb[seqs[bs] * H_ + j]);
}
__global__ void embed_tgt(const int* __restrict__ seqs, const float* __restrict__ emb) {
    int i = blockIdx.x * 256 + threadIdx.x;
    int bs = i >> 9, j = i & 511;
    g_xembbf[i] = __float2bfloat16(emb[seqs[bs] * H_ + j]);
}

// -------------------- fused weight conversion --------------------
#define C0 786432
#define C1 1572864
#define C2 2359296
#define C3 3145728
#define C4 3670016
#define C5 3932160
#define C6 6291456
#define C7 7077888
__global__ void conv_all(const float* w0, const float* w1, const float* w2,
                         const float* w3, const float* w4, const float* w5,
                         const float* w6, const float* w7, const float* w8) {
    long long e = (long long)(blockIdx.x * 256 + threadIdx.x) * 4;
    const float* src; bf16* dst; long long off;
    if      (e < C0) { src = w0; dst = g_Wihf_bf; off = 0; }
    else if (e < C1) { src = w1; dst = g_Wihb_bf; off = C0; }
    else if (e < C2) { src = w2; dst = g_Whhf_bf; off = C1; }
    else if (e < C3) { src = w3; dst = g_Whhb_bf; off = C2; }
    else if (e < C4) { src = w4; dst = g_Uw_bf;   off = C3; }
    else if (e < C5) { src = w5; dst = g_AW_bf;   off = C4; }
    else if (e < C6) { src = w6; dst = g_dWih_bf; off = C5; }
    else if (e < C7) { src = w7; dst = g_dWhh_bf; off = C6; }
    else             { src = w8; dst = g_Wbf;     off = C7; }
    long long i = e - off;
    float4 v = *(const float4*)&src[i];
    dst[i] = __float2bfloat16(v.x);
    dst[i + 1] = __float2bfloat16(v.y);
    dst[i + 2] = __float2bfloat16(v.z);
    dst[i + 3] = __float2bfloat16(v.w);
}

// -------------------- flexible bf16 mma GEMM: C[2048, ...] = A@W^T + bias --------------------
template<int OUT_BF>
__global__ __launch_bounds__(256) void mma_gemm(const bf16* __restrict__ A, int lda,
                                                const bf16* __restrict__ W0,
                                                const bf16* __restrict__ W1,
                                                int ldw, int kwoff,
                                                const float* __restrict__ bias0,
                                                const float* __restrict__ bias1,
                                                float* __restrict__ Cf0, float* __restrict__ Cf1,
                                                bf16* __restrict__ Cb, int ldc, int K) {
    __shared__ bf16 As[128][40];
    __shared__ bf16 Bs[128][40];
    const bf16* W = blockIdx.z ? W1 : W0;
    const float* bias = blockIdx.z ? bias1 : bias0;
    float* Cf = blockIdx.z ? Cf1 : Cf0;
    int tid = threadIdx.x, lane = tid & 31, wid = tid >> 5;
    int wm = wid & 3, wn = wid >> 2;
    int row0 = blockIdx.y * 128, col0 = blockIdx.x * 128;
    float acc[2][8][4];
#pragma unroll
    for (int mt = 0; mt < 2; mt++)
#pragma unroll
        for (int nt = 0; nt < 8; nt++)
#pragma unroll
            for (int c = 0; c < 4; c++) acc[mt][nt][c] = 0.f;

    for (int k0 = 0; k0 < K; k0 += 32) {
        int r = tid >> 2, c = tid & 3;
        *(uint4*)&As[r][c * 8] = *(const uint4*)&A[(row0 + r) * lda + k0 + c * 8];
        *(uint4*)&As[r + 64][c * 8] = *(const uint4*)&A[(row0 + r + 64) * lda + k0 + c * 8];
        *(uint4*)&Bs[r][c * 8] = *(const uint4*)&W[(col0 + r) * ldw + kwoff + k0 + c * 8];
        *(uint4*)&Bs[r + 64][c * 8] = *(const uint4*)&W[(col0 + r + 64) * ldw + kwoff + k0 + c * 8];
        __syncthreads();
#pragma unroll
        for (int kk = 0; kk < 2; kk++) {
            int kb = kk * 16;
            uint32_t af[2][4];
#pragma unroll
            for (int mt = 0; mt < 2; mt++)
                ldm_x4(af[mt], cvsm(&As[wm * 32 + mt * 16 + (lane & 15)][kb + ((lane & 16) ? 8 : 0)]));
            uint32_t bfr[8][2];
#pragma unroll
            for (int np = 0; np < 4; np++) {
                uint32_t t4[4];
                ldm_x4(t4, cvsm(&Bs[wn * 64 + np * 16 + (lane & 7) + ((lane & 16) ? 8 : 0)][kb + ((lane & 8) ? 8 : 0)]));
                bfr[np * 2][0] = t4[0]; bfr[np * 2][1] = t4[1];
                bfr[np * 2 + 1][0] = t4[2]; bfr[np * 2 + 1][1] = t4[3];
            }
#pragma unroll
            for (int mt = 0; mt < 2; mt++)
#pragma unroll
                for (int nt = 0; nt < 8; nt++)
                    mma16816(acc[mt][nt], af[mt], bfr[nt]);
        }
        __syncthreads();
    }
#pragma unroll
    for (int mt = 0; mt < 2; mt++)
#pragma unroll
        for (int nt = 0; nt < 8; nt++) {
            int cb = col0 + wn * 64 + nt * 8 + (lane & 3) * 2;
            float b0 = bias[cb], b1 = bias[cb + 1];
#pragma unroll
            for (int h = 0; h < 2; h++) {
                int row = row0 + wm * 32 + mt * 16 + (lane >> 2) + h * 8;
                float v0 = acc[mt][nt][h * 2] + b0;
                float v1 = acc[mt][nt][h * 2 + 1] + b1;
                if (OUT_BF) {
                    Cb[row * ldc + cb] = __float2bfloat16(v0);
                    Cb[row * ldc + cb + 1] = __float2bfloat16(v1);
                } else {
                    Cf[row * ldc + cb] = v0;
                    Cf[row * ldc + cb + 1] = v1;
                }
            }
        }
}

// -------------------- persistent encoder: 128 blocks x 256 thr, gate-split --------------------
__global__ __launch_bounds__(256) void enc_persist(const float* __restrict__ bhh_f,
                                                   const float* __restrict__ bhh_b,
                                                   const int* __restrict__ slen) {
    extern __shared__ char smem[];
    bf16 (*Wsm)[520] = (bf16(*)[520])smem;                          // 24 rows
    bf16 (*Hsm)[520] = (bf16(*)[520])(smem + 24 * 520 * 2);         // 32 rows
    float (*gh_sm)[32][8] = (float(*)[32][8])(smem + 56 * 520 * 2); // [3][32][8]
    int bid = blockIdx.x, tid = threadIdx.x, lane = tid & 31, w = tid >> 5;
    int dir = bid >> 6, jt = bid & 63;
    const bf16* Wg = dir ? g_Whhb_bf : g_Whhf_bf;
    const float* bhh = dir ? bhh_b : bhh_f;
    const float* gx = dir ? g_gxb : g_gxf;
    int wm = w & 1, grp = w >> 1;

    for (int i = tid; i < 24 * 64; i += 256) {
        int r = i >> 6, ch = i & 63;
        int grow = (r >> 3) * 512 + jt * 8 + (r & 7);
        *(uint4*)&Wsm[r][ch * 8] = *(const uint4*)&Wg[grow * 512 + ch * 8];
    }
    __syncthreads();

    for (int t = 0; t < S_; t++) {
        int rd = t & 1, wr = rd ^ 1;
        for (int i = tid; i < 32 * 64; i += 256) {
            int r = i >> 6, ch = i & 63;
            cpa16(cvsm(&Hsm[r][ch * 8]), &g_hencbf[dir][rd][r * 512 + ch * 8]);
        }
        asm volatile("cp.async.commit_group;");
        asm volatile("cp.async.wait_group 0;");
        __syncthreads();
        if (grp < 3) {
            float acc[4] = {0.f, 0.f, 0.f, 0.f};
#pragma unroll 4
            for (int ks = 0; ks < 32; ks++) {
                uint32_t a4[4], b2[2];
                ldm_x4(a4, cvsm(&Hsm[16 * wm + (lane & 15)][ks * 16 + ((lane & 16) ? 8 : 0)]));
                ldm_x2(b2, cvsm(&Wsm[grp * 8 + (lane & 7)][ks * 16 + ((lane & 8) ? 8 : 0)]));
                mma16816(acc, a4, b2);
            }
            int r0 = wm * 16 + (lane >> 2);
            int c0 = (lane & 3) * 2;
            gh_sm[grp][r0][c0] = acc[0];
            gh_sm[grp][r0][c0 + 1] = acc[1];
            gh_sm[grp][r0 + 8][c0] = acc[2];
            gh_sm[grp][r0 + 8][c0 + 1] = acc[3];
        }
        __syncthreads();
        {
            int b = tid >> 3, jj = tid & 7;
            int j = jt * 8 + jj;
            int tf = dir ? (63 - t) : t;
            bool m = tf < slen[b];
            int base = (b * 64 + tf) * 1536;
            float ghr = gh_sm[0][b][jj] + bhh[j];
            float ghz = gh_sm[1][b][jj] + bhh[512 + j];
            float ghn = gh_sm[2][b][jj] + bhh[1024 + j];
            float h = g_henc[dir][rd][b * 512 + j];
            float r = sigf(gx[base + j] + ghr);
            float z = sigf(gx[base + 512 + j] + ghz);
            float n = tanhf(gx[base + 1024 + j] + r * ghn);
            float hn = (1.f - z) * n + z * h;
            float hout = m ? hn : h;
            g_henc[dir][wr][b * 512 + j] = hout;
            g_hencbf[dir][wr][b * 512 + j] = __float2bfloat16(hout);
            g_srchidbf[(b * 64 + tf) * 1024 + dir * 512 + j] = __float2bfloat16(m ? hn : 0.f);
        }
        sem_arrive_block(&g_semE);
        sem_wait_block(&g_semE, 128u * (t + 1));
    }
}

// -------------------- persistent decoder: 96 blocks, split semaphores --------------------
// blocks 0..31  : attention (one batch each)
// blocks 32..95 : gemm blocks (8-col j-slice): a-GEMM (early signal), gh under attention,
//                 ctx-GEMM + pointwise
__global__ __launch_bounds__(256) void dec_persist(const float* __restrict__ Ab,
                                                   const float* __restrict__ Av,
                                                   const float* __restrict__ dbhh,
                                                   const int* __restrict__ slen,
                                                   const int* __restrict__ tlen) {
    extern __shared__ char smem[];
    int bid = blockIdx.x, tid = threadIdx.x, lane = tid & 31, w = tid >> 5;

    if (bid < 32) {
        int b = bid;
        bf16 (*Uhc)[520] = (bf16(*)[520])smem;                          // 64 rows
        bf16 (*SHc)[1048] = (bf16(*)[1048])(smem + 64 * 520 * 2);       // 64 rows
        float* a_sm = (float*)(smem + 64 * 520 * 2 + 64 * 1048 * 2);    // 512
        float* wts = a_sm + 512;                                        // 64
        float* Ab_sm = wts + 64;                                        // 512
        float* Av_sm = Ab_sm + 512;                                     // 512
        for (int i = tid; i < 64 * 64; i += 256) {
            int s = i >> 6, ch = i & 63;
            *(uint4*)&Uhc[s][ch * 8] = *(const uint4*)&g_Uhbf[(b * 64 + s) * 512 + ch * 8];
        }
        for (int i = tid; i < 64 * 128; i += 256) {
            int s = i >> 7, ch = i & 127;
            *(uint4*)&SHc[s][ch * 8] = *(const uint4*)&g_srchidbf[(b * 64 + s) * 1024 + ch * 8];
        }
        for (int j = tid; j < 512; j += 256) { Ab_sm[j] = Ab[j]; Av_sm[j] = Av[j]; }
        int L = slen[b];
        for (int t = 0; t < T_; t++) {
            sem_wait_block(&g_semA, 64u * (t + 1));
            for (int j = tid; j < 512; j += 256) a_sm[j] = g_a[b * 512 + j] + Ab_sm[j];
            __syncthreads();
#pragma unroll
            for (int si = 0; si < 8; si++) {
                int s = w * 8 + si;
                float p = 0.f;
#pragma unroll 4
                for (int j = lane; j < 512; j += 32)
                    p += Av_sm[j] * tanha(__bfloat162float(Uhc[s][j]) + a_sm[j]);
#pragma unroll
                for (int o = 16; o > 0; o >>= 1) p += __shfl_xor_sync(0xffffffffu, p, o);
                if (lane == 0) wts[s] = (s < L) ? p : p - 1e9f;
            }
            __syncthreads();
            if (w == 0) {
                float e0 = wts[lane], e1 = wts[lane + 32];
                float m = fmaxf(e0, e1);
#pragma unroll
                for (int o = 16; o > 0; o >>= 1) m = fmaxf(m, __shfl_xor_sync(0xffffffffu, m, o));
                float x0 = __expf(e0 - m), x1 = __expf(e1 - m);
                float sm = x0 + x1;
#pragma unroll
                for (int o = 16; o > 0; o >>= 1) sm += __shfl_xor_sync(0xffffffffu, sm, o);
                float inv = 1.f / sm;
                wts[lane] = x0 * inv;
                wts[lane + 32] = x1 * inv;
            }
            __syncthreads();
            for (int j = tid; j < 1024; j += 256) {
                float c0 = 0.f, c1 = 0.f;
#pragma unroll 16
                for (int s = 0; s < 64; s += 2) {
                    c0 += wts[s] * __bfloat162float(SHc[s][j]);
                    c1 += wts[s + 1] * __bfloat162float(SHc[s + 1][j]);
                }
                g_cbf[b * 1024 + j] = __float2bfloat16(c0 + c1);
            }
            sem_arrive_block(&g_semB);
        }
    } else {
        int gid = bid - 32;
        bf16 (*Wih)[1032] = (bf16(*)[1032])smem;                                  // 24 rows (ctx)
        bf16 (*Whh)[520] = (bf16(*)[520])(smem + 24 * 1032 * 2);                  // 24 rows
        bf16 (*AWc)[520] = (bf16(*)[520])(smem + 24 * 1032 * 2 + 24 * 520 * 2);   // 8 rows
        bf16 (*Asm)[1048] = (bf16(*)[1048])(smem + 24 * 1032 * 2 + 32 * 520 * 2); // 32 rows
        float (*gh_sm)[32][8] = (float(*)[32][8])(smem + 24 * 1032 * 2 + 32 * 520 * 2 + 32 * 1048 * 2);
        float (*gx_sm)[32][8] = (float(*)[32][8])((char*)gh_sm + 3 * 32 * 8 * 4);
        for (int i = tid; i < 24 * 128; i += 256) {
            int r = i >> 7, ch = i & 127;
            int grow = (r >> 3) * 512 + gid * 8 + (r & 7);
            *(uint4*)&Wih[r][ch * 8] = *(const uint4*)&g_dWih_bf[grow * 1536 + 512 + ch * 8];
        }
        for (int i = tid; i < 24 * 64; i += 256) {
            int r = i >> 6, ch = i & 63;
            int grow = (r >> 3) * 512 + gid * 8 + (r & 7);
            *(uint4*)&Whh[r][ch * 8] = *(const uint4*)&g_dWhh_bf[grow * 512 + ch * 8];
        }
        for (int i = tid; i < 8 * 64; i += 256) {
            int r = i >> 6, ch = i & 63;
            *(uint4*)&AWc[r][ch * 8] = *(const uint4*)&g_AW_bf[(gid * 8 + r) * 512 + ch * 8];
        }
        int wm = w & 1, grp = w >> 1;    // 8 warps: 2 m-tiles x {a, r, z, n}
        for (int t = 0; t < T_; t++) {
            // ---- stage A: load h; grp0 -> a (early signal); grp1..3 -> gh (overlaps attn) ----
            for (int i = tid; i < 32 * 64; i += 256) {
                int r = i >> 6, ch = i & 63;
                cpa16(cvsm(&Asm[r][ch * 8]), &g_hdecbf[r * 512 + ch * 8]);
            }
            asm volatile("cp.async.commit_group;");
            asm volatile("cp.async.wait_group 0;");
            __syncthreads();
            if (grp == 0) {
                float acc[4] = {0.f, 0.f, 0.f, 0.f};
#pragma unroll 4
                for (int ks = 0; ks < 32; ks++) {
                    uint32_t a4[4], b2[2];
                    ldm_x4(a4, cvsm(&Asm[16 * wm + (lane & 15)][ks * 16 + ((lane & 16) ? 8 : 0)]));
                    ldm_x2(b2, cvsm(&AWc[(lane & 7)][ks * 16 + ((lane & 8) ? 8 : 0)]));
                    mma16816(acc, a4, b2);
                }
                int r0 = wm * 16 + (lane >> 2);
                int c0 = gid * 8 + (lane & 3) * 2;
                g_a[r0 * 512 + c0] = acc[0];
                g_a[r0 * 512 + c0 + 1] = acc[1];
                g_a[(r0 + 8) * 512 + c0] = acc[2];
                g_a[(r0 + 8) * 512 + c0 + 1] = acc[3];
                __threadfence();
                asm volatile("bar.sync 1, 64;" ::: "memory");
                if (tid == 0) sem_signal(&g_semA);       // attention may start
            } else {
                int g = grp - 1;
                float acc[4] = {0.f, 0.f, 0.f, 0.f};
#pragma unroll 4
                for (int ks = 0; ks < 32; ks++) {
                    uint32_t a4[4], b2[2];
                    ldm_x4(a4, cvsm(&Asm[16 * wm + (lane & 15)][ks * 16 + ((lane & 16) ? 8 : 0)]));
                    ldm_x2(b2, cvsm(&Whh[g * 8 + (lane & 7)][ks * 16 + ((lane & 8) ? 8 : 0)]));
                    mma16816(acc, a4, b2);
                }
                int r0 = wm * 16 + (lane >> 2);
                int c0 = (lane & 3) * 2;
                gh_sm[g][r0][c0] = acc[0];
                gh_sm[g][r0][c0 + 1] = acc[1];
                gh_sm[g][r0 + 8][c0] = acc[2];
                gh_sm[g][r0 + 8][c0 + 1] = acc[3];
            }
            // ---- wait for context ----
            sem_wait_block(&g_semB, 32u * (t + 1));
            for (int i = tid; i < 32 * 128; i += 256) {
                int r = i >> 7, ch = i & 127;
                cpa16(cvsm(&Asm[r][ch * 8]), &g_cbf[r * 1024 + ch * 8]);
            }
            asm volatile("cp.async.commit_group;");
            asm volatile("cp.async.wait_group 0;");
            __syncthreads();
            if (grp >= 1) {
                int g = grp - 1;
                float acc[4] = {0.f, 0.f, 0.f, 0.f};
#pragma unroll 4
                for (int ks = 0; ks < 64; ks++) {
                    uint32_t a4[4], b2[2];
                    ldm_x4(a4, cvsm(&Asm[16 * wm + (lane & 15)][ks * 16 + ((lane & 16) ? 8 : 0)]));
                    ldm_x2(b2, cvsm(&Wih[g * 8 + (lane & 7)][ks * 16 + ((lane & 8) ? 8 : 0)]));
                    mma16816(acc, a4, b2);
                }
                int r0 = wm * 16 + (lane >> 2);
                int c0 = (lane & 3) * 2;
                gx_sm[g][r0][c0] = acc[0];
                gx_sm[g][r0][c0 + 1] = acc[1];
                gx_sm[g][r0 + 8][c0] = acc[2];
                gx_sm[g][r0 + 8][c0 + 1] = acc[3];
            }
            __syncthreads();
            // ---- pointwise: 256 threads, one (b, j) element each ----
            {
                int b = tid >> 3, jj = tid & 7;
                int j = gid * 8 + jj;
                bool m = t < tlen[b];
                const float* ge = g_gxemb + (b * 64 + t) * 1536;
                float gxr = gx_sm[0][b][jj] + ge[j];
                float gxz = gx_sm[1][b][jj] + ge[512 + j];
                float gxn = gx_sm[2][b][jj] + ge[1024 + j];
                float ghr = gh_sm[0][b][jj] + dbhh[j];
                float ghz = gh_sm[1][b][jj] + dbhh[512 + j];
                float ghn = gh_sm[2][b][jj] + dbhh[1024 + j];
                float h = g_hdec[b * 512 + j];
                float r = sigf(gxr + ghr);
                float z = sigf(gxz + ghz);
                float n = tanhf(gxn + r * ghn);
                float hn = (1.f - z) * n + z * h;
                float hout = m ? hn : h;
                g_hdec[b * 512 + j] = hout;
                g_hdecbf[b * 512 + j] = __float2bfloat16(hout);
                g_decbf[(b * 64 + t) * 512 + j] = __float2bfloat16(m ? hn : 0.f);
            }
            sem_arrive_block(&g_semC);
            sem_wait_block(&g_semC, 64u * (t + 1));      // gemm-group barrier on h
        }
    }
}

// -------------------- logits GEMM (cp.async 2-stage) + exp-sum + pick --------------------
__global__ __launch_bounds__(256) void logits_mma(const float* __restrict__ bias,
                                                  const int* __restrict__ tseq) {
    __shared__ bf16 As[2][128][40];
    __shared__ bf16 Bs[2][128][40];
    __shared__ float rowsum[128][2];
    int tid = threadIdx.x, lane = tid & 31, wid = tid >> 5;
    int wm = wid & 3, wn = wid >> 2;
    int row0 = blockIdx.y * 128, col0 = blockIdx.x * 128;
    int r = tid >> 2, c = tid & 3;
    float acc[2][8][4];
#pragma unroll
    for (int mt = 0; mt < 2; mt++)
#pragma unroll
        for (int nt = 0; nt < 8; nt++)
#pragma unroll
            for (int cc = 0; cc < 4; cc++) acc[mt][nt][cc] = 0.f;

#define ISSUE(kt, st)                                                                  \
    do {                                                                               \
        int k0_ = (kt) * 32;                                                           \
        cpa16(cvsm(&As[st][r][c * 8]), &g_decbf[(row0 + r) * 512 + k0_ + c * 8]);      \
        cpa16(cvsm(&As[st][r + 64][c * 8]), &g_decbf[(row0 + r + 64) * 512 + k0_ + c * 8]); \
        cpa16(cvsm(&Bs[st][r][c * 8]), &g_Wbf[(col0 + r) * 512 + k0_ + c * 8]);        \
        cpa16(cvsm(&Bs[st][r + 64][c * 8]), &g_Wbf[(col0 + r + 64) * 512 + k0_ + c * 8]); \
        asm volatile("cp.async.commit_group;");                                        \
    } while (0)

    ISSUE(0, 0);
    for (int kt = 0; kt < 16; kt++) {
        int st = kt & 1;
        if (kt < 15) {
            ISSUE(kt + 1, st ^ 1);
            asm volatile("cp.async.wait_group 1;");
        } else {
            asm volatile("cp.async.wait_group 0;");
        }
        __syncthreads();
#pragma unroll
        for (int kk = 0; kk < 2; kk++) {
            int kb = kk * 16;
            uint32_t af[2][4];
#pragma unroll
            for (int mt = 0; mt < 2; mt++)
                ldm_x4(af[mt], cvsm(&As[st][wm * 32 + mt * 16 + (lane & 15)][kb + ((lane & 16) ? 8 : 0)]));
            uint32_t bfr[8][2];
#pragma unroll
            for (int np = 0; np < 4; np++) {
                uint32_t t4[4];
                ldm_x4(t4, cvsm(&Bs[st][wn * 64 + np * 16 + (lane & 7) + ((lane & 16) ? 8 : 0)][kb + ((lane & 8) ? 8 : 0)]));
                bfr[np * 2][0] = t4[0]; bfr[np * 2][1] = t4[1];
                bfr[np * 2 + 1][0] = t4[2]; bfr[np * 2 + 1][1] = t4[3];
            }
#pragma unroll
            for (int mt = 0; mt < 2; mt++)
#pragma unroll
                for (int nt = 0; nt < 8; nt++)
                    mma16816(acc[mt][nt], af[mt], bfr[nt]);
        }
        __syncthreads();
    }
#undef ISSUE

    float sums[2][2] = {{0.f, 0.f}, {0.f, 0.f}};
    int gl[2][2];
#pragma unroll
    for (int mt = 0; mt < 2; mt++)
#pragma unroll
        for (int h = 0; h < 2; h++) {
            int row = row0 + wm * 32 + mt * 16 + (lane >> 2) + h * 8;
            int tt = row & 63;
            gl[mt][h] = (tt < T_ - 1) ? tseq[(row >> 6) * T_ + tt + 1] : 0;
        }
#pragma unroll
    for (int mt = 0; mt < 2; mt++)
#pragma unroll
        for (int nt = 0; nt < 8; nt++) {
            int cb = col0 + wn * 64 + nt * 8 + (lane & 3) * 2;
            float b0 = bias[cb], b1 = bias[cb + 1];
#pragma unroll
            for (int h = 0; h < 2; h++) {
                float v0 = acc[mt][nt][h * 2] + b0;
                float v1 = acc[mt][nt][h * 2 + 1] + b1;
                sums[mt][h] += __expf(v0) + __expf(v1);
                int row = row0 + wm * 32 + mt * 16 + (lane >> 2) + h * 8;
                if (cb == gl[mt][h]) g_picked[row] = v0;
                if (cb + 1 == gl[mt][h]) g_picked[row] = v1;
            }
        }
#pragma unroll
    for (int mt = 0; mt < 2; mt++)
#pragma unroll
        for (int h = 0; h < 2; h++) {
            float s = sums[mt][h];
            s += __shfl_xor_sync(0xffffffffu, s, 1);
            s += __shfl_xor_sync(0xffffffffu, s, 2);
            if ((lane & 3) == 0)
                rowsum[wm * 32 + mt * 16 + (lane >> 2) + h * 8][wn] = s;
        }
    __syncthreads();
    if (tid < 128)
        g_partial[(row0 + tid) * NVT + blockIdx.x] = rowsum[tid][0] + rowsum[tid][1];
}

__global__ void rowloss_kernel(const int* __restrict__ tseq) {
    int r = blockIdx.x, tid = threadIdx.x;
    float s = 0.f;
    for (int v = tid; v < NVT; v += 128) s += g_partial[r * NVT + v];
#pragma unroll
    for (int o = 16; o > 0; o >>= 1) s += __shfl_xor_sync(0xffffffffu, s, o);
    __shared__ float w[4];
    if ((tid & 31) == 0) w[tid >> 5] = s;
    __syncthreads();
    if (tid == 0) {
        float sum = w[0] + w[1] + w[2] + w[3];
        int b = r >> 6, t = r & 63;
        int g = (t < T_ - 1) ? tseq[b * T_ + t + 1] : 0;
        if (g != 0) { g_rowloss[r] = logf(sum) - g_picked[r]; g_rowvalid[r] = 1.f; }
        else        { g_rowloss[r] = 0.f;                     g_rowvalid[r] = 0.f; }
    }
}

__global__ void final_kernel(float* __restrict__ out) {
    int tid = threadIdx.x;
    float s = 0.f, c = 0.f;
    for (int r = tid; r < ROWS; r += 256) { s += g_rowloss[r]; c += g_rowvalid[r]; }
#pragma unroll
    for (int o = 16; o > 0; o >>= 1) {
        s += __shfl_xor_sync(0xffffffffu, s, o);
        c += __shfl_xor_sync(0xffffffffu, c, o);
    }
    __shared__ float ws[8], wc[8];
    if ((tid & 31) == 0) { ws[tid >> 5] = s; wc[tid >> 5] = c; }
    __syncthreads();
    if (tid == 0) {
        float S = 0.f, C = 0.f;
        for (int i = 0; i < 8; i++) { S += ws[i]; C += wc[i]; }
        out[0] = S / C;
    }
}

// -------------------- launch --------------------
extern "C" void kernel_launch(void* const* d_in, const int* in_sizes, int n_in,
                              void* d_out, int out_size) {
    const int*   src_seqs = (const int*)d_in[0];
    const int*   src_len  = (const int*)d_in[1];
    const int*   tgt_seqs = (const int*)d_in[2];
    const int*   tgt_len  = (const int*)d_in[3];
    const float* src_emb  = (const float*)d_in[4];
    const float* eWih_f   = (const float*)d_in[5];
    const float* eWhh_f   = (const float*)d_in[6];
    const float* ebih_f   = (const float*)d_in[7];
    const float* ebhh_f   = (const float*)d_in[8];
    const float* eWih_b   = (const float*)d_in[9];
    const float* eWhh_b   = (const float*)d_in[10];
    const float* ebih_b   = (const float*)d_in[11];
    const float* ebhh_b   = (const float*)d_in[12];
    const float* tgt_emb  = (const float*)d_in[13];
    const float* dWih     = (const float*)d_in[14];
    const float* dWhh     = (const float*)d_in[15];
    const float* dbih     = (const float*)d_in[16];
    const float* dbhh     = (const float*)d_in[17];
    const float* U_w      = (const float*)d_in[18];
    const float* U_b      = (const float*)d_in[19];
    const float* A_W      = (const float*)d_in[20];
    const float* A_b      = (const float*)d_in[21];
    const float* A_v      = (const float*)d_in[22];
    const float* out_w    = (const float*)d_in[23];
    const float* out_b    = (const float*)d_in[24];

    bf16 *wihf, *wihb, *uw, *dwih, *esrc, *srchid, *uhbf, *xemb;
    float *gxf, *gxb, *gxe;
    cudaGetSymbolAddress((void**)&wihf, g_Wihf_bf);
    cudaGetSymbolAddress((void**)&wihb, g_Wihb_bf);
    cudaGetSymbolAddress((void**)&uw, g_Uw_bf);
    cudaGetSymbolAddress((void**)&dwih, g_dWih_bf);
    cudaGetSymbolAddress((void**)&esrc, g_esrcbf);
    cudaGetSymbolAddress((void**)&srchid, g_srchidbf);
    cudaGetSymbolAddress((void**)&uhbf, g_Uhbf);
    cudaGetSymbolAddress((void**)&xemb, g_xembbf);
    cudaGetSymbolAddress((void**)&gxf, g_gxf);
    cudaGetSymbolAddress((void**)&gxb, g_gxb);
    cudaGetSymbolAddress((void**)&gxe, g_gxemb);

    cudaFuncSetAttribute(enc_persist, cudaFuncAttributeMaxDynamicSharedMemorySize, 61312);
    cudaFuncSetAttribute(dec_persist, cudaFuncAttributeMaxDynamicSharedMemorySize, 207104);

    init_states<<<64, 256>>>();
    embed_src<<<4096, 256>>>(src_seqs, src_emb);
    embed_tgt<<<4096, 256>>>(tgt_seqs, tgt_emb);
    conv_all<<<22912, 256>>>(eWih_f, eWih_b, eWhh_f, eWhh_b, U_w, A_W, dWih, dWhh, out_w);

    // encoder input gates (both dirs)
    mma_gemm<0><<<dim3(12, 16, 2), 256>>>(esrc, H_, wihf, wihb, H_, 0,
                                          ebih_f, ebih_b, gxf, gxb, (bf16*)0, H3_, H_);
    // decoder embedding gate-input precompute (includes dbih)
    mma_gemm<0><<<dim3(12, 16, 1), 256>>>(xemb, H_, dwih, dwih, H3_, 0,
                                          dbih, dbih, gxe, gxe, (bf16*)0, H3_, H_);

    enc_persist<<<128, 256, 61312>>>(ebhh_f, ebhh_b, src_len);

    // Uh = srchid @ U_w^T + U_b (bf16 out)
    mma_gemm<1><<<dim3(4, 16, 1), 256>>>(srchid, 1024, uw, uw, 1024, 0,
                                         U_b, U_b, (float*)0, (float*)0, uhbf, H_, 1024);

    dec_persist<<<96, 256, 207104>>>(A_b, A_v, dbhh, src_len, tgt_len);

    logits_mma<<<dim3(NVT, 16), 256>>>(out_b, tgt_seqs);
    rowloss_kernel<<<ROWS, 128>>>(tgt_seqs);
    final_kernel<<<1, 256>>>((float*)d_out);
}

// round 10
// speedup vs baseline: 1.9947x; 1.0630x over previous
#include <cuda_runtime.h>
#include <cuda_bf16.h>
#include <math.h>
#include <stdint.h>

#define B_ 32
#define S_ 64
#define T_ 64
#define H_ 512
#define H3_ 1536
#define V_ 32000
#define NVT 250
#define ROWS 2048

typedef __nv_bfloat16 bf16;

// -------------------- device scratch --------------------
__device__ bf16 g_esrcbf[ROWS * H_];
__device__ float g_gxf[ROWS * H3_];
__device__ float g_gxb[ROWS * H3_];
__device__ bf16 g_srchidbf[ROWS * 1024];
__device__ bf16 g_Uhbf[ROWS * H_];
__device__ float g_henc[2][2][B_ * H_];
__device__ bf16  g_hencbf[2][2][B_ * H_];
__device__ float g_hdec[B_ * H_];
__device__ bf16  g_hdecbf[B_ * H_];
__device__ float g_a[B_ * H_];
__device__ bf16 g_xembbf[ROWS * H_];
__device__ float g_gxemb[ROWS * H3_];     // emb@Wih_e^T + dbih for every (b,t)
__device__ bf16 g_cbf[B_ * 1024];
__device__ bf16 g_decbf[ROWS * H_];
__device__ bf16 g_Wihf_bf[H3_ * H_];
__device__ bf16 g_Wihb_bf[H3_ * H_];
__device__ bf16 g_Whhf_bf[H3_ * H_];
__device__ bf16 g_Whhb_bf[H3_ * H_];
__device__ bf16 g_Uw_bf[H_ * 1024];
__device__ bf16 g_AW_bf[H_ * H_];
__device__ bf16 g_dWih_bf[H3_ * H3_];
__device__ bf16 g_dWhh_bf[H3_ * H_];
__device__ bf16 g_Wbf[V_ * H_];
__device__ float g_partial[ROWS * NVT];
__device__ float g_picked[ROWS];
__device__ float g_rowloss[ROWS];
__device__ float g_rowvalid[ROWS];
__device__ unsigned g_semA, g_semB, g_semC, g_semE;

__device__ __forceinline__ float sigf(float x) { return 1.f / (1.f + __expf(-x)); }
__device__ __forceinline__ float tanha(float x) {
    float y; asm("tanh.approx.f32 %0,%1;" : "=f"(y) : "f"(x)); return y;
}

// -------------------- monotonic semaphores --------------------
__device__ __forceinline__ void sem_signal(unsigned* s) {
    asm volatile("red.release.gpu.global.add.u32 [%0],1;" :: "l"(s) : "memory");
}
__device__ __forceinline__ void sem_spin(unsigned* s, unsigned target) {
    unsigned v;
    do { asm volatile("ld.acquire.gpu.global.u32 %0,[%1];" : "=r"(v) : "l"(s) : "memory"); }
    while (v < target);
}
__device__ __forceinline__ void sem_arrive_block(unsigned* s) {
    __threadfence();
    __syncthreads();
    if (threadIdx.x == 0) sem_signal(s);
}
__device__ __forceinline__ void sem_wait_block(unsigned* s, unsigned target) {
    if (threadIdx.x == 0) sem_spin(s, target);
    __syncthreads();
}

__device__ __forceinline__ uint32_t cvsm(const void* p) {
    return (uint32_t)__cvta_generic_to_shared(p);
}
__device__ __forceinline__ void ldm_x4(uint32_t* r, uint32_t a) {
    asm volatile("ldmatrix.sync.aligned.m8n8.x4.shared.b16 {%0,%1,%2,%3},[%4];\n"
                 : "=r"(r[0]), "=r"(r[1]), "=r"(r[2]), "=r"(r[3]) : "r"(a));
}
__device__ __forceinline__ void ldm_x2(uint32_t* r, uint32_t a) {
    asm volatile("ldmatrix.sync.aligned.m8n8.x2.shared.b16 {%0,%1},[%2];\n"
                 : "=r"(r[0]), "=r"(r[1]) : "r"(a));
}
__device__ __forceinline__ void mma16816(float* d, const uint32_t* a, const uint32_t* b) {
    asm volatile("mma.sync.aligned.m16n8k16.row.col.f32.bf16.bf16.f32 "
                 "{%0,%1,%2,%3},{%4,%5,%6,%7},{%8,%9},{%0,%1,%2,%3};\n"
                 : "+f"(d[0]), "+f"(d[1]), "+f"(d[2]), "+f"(d[3])
                 : "r"(a[0]), "r"(a[1]), "r"(a[2]), "r"(a[3]), "r"(b[0]), "r"(b[1]));
}
__device__ __forceinline__ void cpa16(uint32_t dst, const void* src) {
    asm volatile("cp.async.cg.shared.global [%0], [%1], 16;\n" :: "r"(dst), "l"(src));
}

// -------------------- init / embeds --------------------
__global__ void init_states() {
    int i = blockIdx.x * 256 + threadIdx.x;
    if (i < B_ * H_) {
        g_henc[0][0][i] = 0.f; g_henc[1][0][i] = 0.f;
        g_hencbf[0][0][i] = __float2bfloat16(0.f);
        g_hencbf[1][0][i] = __float2bfloat16(0.f);
        g_hdec[i] = 0.f;
        g_hdecbf[i] = __float2bfloat16(0.f);
    }
    if (i == 0) { g_semA = 0u; g_semB = 0u; g_semC = 0u; g_semE = 0u; }
}

// both source and target embeddings in one launch
__global__ void embed_all(const int* __restrict__ sseqs, const float* __restrict__ semb,
                          const int* __restrict__ tseqs, const float* __restrict__ temb) {
    int gi = blockIdx.x * 256 + threadIdx.x;
    int half = gi >> 20;          // 4096 blocks * 256 = 2^20 per half
    int i = gi & 1048575;
    int bs = i >> 9, j = i & 511;
    if (half == 0) g_esrcbf[i] = __float2bfloat16(semb[sseqs[bs] * H_ + j]);
    else           g_xembbf[i] = __float2bfloat16(temb[tseqs[bs] * H_ + j]);
}

// -------------------- fused weight conversion --------------------
#define C0 786432
#define C1 1572864
#define C2 2359296
#define C3 3145728
#define C4 3670016
#define C5 3932160
#define C6 6291456
#define C7 7077888
__global__ void conv_all(const float* w0, const float* w1, const float* w2,
                         const float* w3, const float* w4, const float* w5,
                         const float* w6, const float* w7, const float* w8) {
    long long e = (long long)(blockIdx.x * 256 + threadIdx.x) * 4;
    const float* src; bf16* dst; long long off;
    if      (e < C0) { src = w0; dst = g_Wihf_bf; off = 0; }
    else if (e < C1) { src = w1; dst = g_Wihb_bf; off = C0; }
    else if (e < C2) { src = w2; dst = g_Whhf_bf; off = C1; }
    else if (e < C3) { src = w3; dst = g_Whhb_bf; off = C2; }
    else if (e < C4) { src = w4; dst = g_Uw_bf;   off = C3; }
    else if (e < C5) { src = w5; dst = g_AW_bf;   off = C4; }
    else if (e < C6) { src = w6; dst = g_dWih_bf; off = C5; }
    else if (e < C7) { src = w7; dst = g_dWhh_bf; off = C6; }
    else             { src = w8; dst = g_Wbf;     off = C7; }
    long long i = e - off;
    float4 v = *(const float4*)&src[i];
    dst[i] = __float2bfloat16(v.x);
    dst[i + 1] = __float2bfloat16(v.y);
    dst[i + 2] = __float2bfloat16(v.z);
    dst[i + 3] = __float2bfloat16(v.w);
}

// -------------------- gx_all: all three input-gate GEMMs in one launch --------------------
// z=0: gxf = esrc@Wihf^T + bih_f ; z=1: gxb = esrc@Wihb^T + bih_b
// z=2: gxemb = xemb@dWih[:, :512]^T + dbih
__global__ __launch_bounds__(256) void gx_all(const float* __restrict__ bih_f,
                                              const float* __restrict__ bih_b,
                                              const float* __restrict__ dbih) {
    __shared__ bf16 As[128][40];
    __shared__ bf16 Bs[128][40];
    int z = blockIdx.z;
    const bf16* A = (z == 2) ? g_xembbf : g_esrcbf;
    const bf16* W = (z == 0) ? g_Wihf_bf : (z == 1) ? g_Wihb_bf : g_dWih_bf;
    int ldw = (z == 2) ? H3_ : H_;
    const float* bias = (z == 0) ? bih_f : (z == 1) ? bih_b : dbih;
    float* C = (z == 0) ? g_gxf : (z == 1) ? g_gxb : g_gxemb;
    int tid = threadIdx.x, lane = tid & 31, wid = tid >> 5;
    int wm = wid & 3, wn = wid >> 2;
    int row0 = blockIdx.y * 128, col0 = blockIdx.x * 128;
    float acc[2][8][4];
#pragma unroll
    for (int mt = 0; mt < 2; mt++)
#pragma unroll
        for (int nt = 0; nt < 8; nt++)
#pragma unroll
            for (int c = 0; c < 4; c++) acc[mt][nt][c] = 0.f;

    for (int k0 = 0; k0 < H_; k0 += 32) {
        int r = tid >> 2, c = tid & 3;
        *(uint4*)&As[r][c * 8] = *(const uint4*)&A[(row0 + r) * H_ + k0 + c * 8];
        *(uint4*)&As[r + 64][c * 8] = *(const uint4*)&A[(row0 + r + 64) * H_ + k0 + c * 8];
        *(uint4*)&Bs[r][c * 8] = *(const uint4*)&W[(col0 + r) * ldw + k0 + c * 8];
        *(uint4*)&Bs[r + 64][c * 8] = *(const uint4*)&W[(col0 + r + 64) * ldw + k0 + c * 8];
        __syncthreads();
#pragma unroll
        for (int kk = 0; kk < 2; kk++) {
            int kb = kk * 16;
            uint32_t af[2][4];
#pragma unroll
            for (int mt = 0; mt < 2; mt++)
                ldm_x4(af[mt], cvsm(&As[wm * 32 + mt * 16 + (lane & 15)][kb + ((lane & 16) ? 8 : 0)]));
            uint32_t bfr[8][2];
#pragma unroll
            for (int np = 0; np < 4; np++) {
                uint32_t t4[4];
                ldm_x4(t4, cvsm(&Bs[wn * 64 + np * 16 + (lane & 7) + ((lane & 16) ? 8 : 0)][kb + ((lane & 8) ? 8 : 0)]));
                bfr[np * 2][0] = t4[0]; bfr[np * 2][1] = t4[1];
                bfr[np * 2 + 1][0] = t4[2]; bfr[np * 2 + 1][1] = t4[3];
            }
#pragma unroll
            for (int mt = 0; mt < 2; mt++)
#pragma unroll
                for (int nt = 0; nt < 8; nt++)
                    mma16816(acc[mt][nt], af[mt], bfr[nt]);
        }
        __syncthreads();
    }
#pragma unroll
    for (int mt = 0; mt < 2; mt++)
#pragma unroll
        for (int nt = 0; nt < 8; nt++) {
            int cb = col0 + wn * 64 + nt * 8 + (lane & 3) * 2;
            float b0 = bias[cb], b1 = bias[cb + 1];
#pragma unroll
            for (int h = 0; h < 2; h++) {
                int row = row0 + wm * 32 + mt * 16 + (lane >> 2) + h * 8;
                C[row * H3_ + cb] = acc[mt][nt][h * 2] + b0;
                C[row * H3_ + cb + 1] = acc[mt][nt][h * 2 + 1] + b1;
            }
        }
}

// -------------------- Uh GEMM (bf16 out), K=1024 --------------------
__global__ __launch_bounds__(256) void uh_gemm(const float* __restrict__ U_b) {
    __shared__ bf16 As[128][40];
    __shared__ bf16 Bs[128][40];
    int tid = threadIdx.x, lane = tid & 31, wid = tid >> 5;
    int wm = wid & 3, wn = wid >> 2;
    int row0 = blockIdx.y * 128, col0 = blockIdx.x * 128;
    float acc[2][8][4];
#pragma unroll
    for (int mt = 0; mt < 2; mt++)
#pragma unroll
        for (int nt = 0; nt < 8; nt++)
#pragma unroll
            for (int c = 0; c < 4; c++) acc[mt][nt][c] = 0.f;

    for (int k0 = 0; k0 < 1024; k0 += 32) {
        int r = tid >> 2, c = tid & 3;
        *(uint4*)&As[r][c * 8] = *(const uint4*)&g_srchidbf[(row0 + r) * 1024 + k0 + c * 8];
        *(uint4*)&As[r + 64][c * 8] = *(const uint4*)&g_srchidbf[(row0 + r + 64) * 1024 + k0 + c * 8];
        *(uint4*)&Bs[r][c * 8] = *(const uint4*)&g_Uw_bf[(col0 + r) * 1024 + k0 + c * 8];
        *(uint4*)&Bs[r + 64][c * 8] = *(const uint4*)&g_Uw_bf[(col0 + r + 64) * 1024 + k0 + c * 8];
        __syncthreads();
#pragma unroll
        for (int kk = 0; kk < 2; kk++) {
            int kb = kk * 16;
            uint32_t af[2][4];
#pragma unroll
            for (int mt = 0; mt < 2; mt++)
                ldm_x4(af[mt], cvsm(&As[wm * 32 + mt * 16 + (lane & 15)][kb + ((lane & 16) ? 8 : 0)]));
            uint32_t bfr[8][2];
#pragma unroll
            for (int np = 0; np < 4; np++) {
                uint32_t t4[4];
                ldm_x4(t4, cvsm(&Bs[wn * 64 + np * 16 + (lane & 7) + ((lane & 16) ? 8 : 0)][kb + ((lane & 8) ? 8 : 0)]));
                bfr[np * 2][0] = t4[0]; bfr[np * 2][1] = t4[1];
                bfr[np * 2 + 1][0] = t4[2]; bfr[np * 2 + 1][1] = t4[3];
            }
#pragma unroll
            for (int mt = 0; mt < 2; mt++)
#pragma unroll
                for (int nt = 0; nt < 8; nt++)
                    mma16816(acc[mt][nt], af[mt], bfr[nt]);
        }
        __syncthreads();
    }
#pragma unroll
    for (int mt = 0; mt < 2; mt++)
#pragma unroll
        for (int nt = 0; nt < 8; nt++) {
            int cb = col0 + wn * 64 + nt * 8 + (lane & 3) * 2;
            float b0 = U_b[cb], b1 = U_b[cb + 1];
#pragma unroll
            for (int h = 0; h < 2; h++) {
                int row = row0 + wm * 32 + mt * 16 + (lane >> 2) + h * 8;
                g_Uhbf[row * H_ + cb] = __float2bfloat16(acc[mt][nt][h * 2] + b0);
                g_Uhbf[row * H_ + cb + 1] = __float2bfloat16(acc[mt][nt][h * 2 + 1] + b1);
            }
        }
}

// -------------------- persistent encoder: 128 blocks x 256 thr, ILP-2 chains --------------------
__global__ __launch_bounds__(256) void enc_persist(const float* __restrict__ bhh_f,
                                                   const float* __restrict__ bhh_b,
                                                   const int* __restrict__ slen) {
    extern __shared__ char smem[];
    bf16 (*Wsm)[520] = (bf16(*)[520])smem;                          // 24 rows
    bf16 (*Hsm)[520] = (bf16(*)[520])(smem + 24 * 520 * 2);         // 32 rows
    float (*gh_sm)[32][8] = (float(*)[32][8])(smem + 56 * 520 * 2); // [3][32][8]
    int bid = blockIdx.x, tid = threadIdx.x, lane = tid & 31, w = tid >> 5;
    int dir = bid >> 6, jt = bid & 63;
    const bf16* Wg = dir ? g_Whhb_bf : g_Whhf_bf;
    const float* bhh = dir ? bhh_b : bhh_f;
    const float* gx = dir ? g_gxb : g_gxf;
    int wm = w & 1, grp = w >> 1;

    for (int i = tid; i < 24 * 64; i += 256) {
        int r = i >> 6, ch = i & 63;
        int grow = (r >> 3) * 512 + jt * 8 + (r & 7);
        *(uint4*)&Wsm[r][ch * 8] = *(const uint4*)&Wg[grow * 512 + ch * 8];
    }
    __syncthreads();

    for (int t = 0; t < S_; t++) {
        int rd = t & 1, wr = rd ^ 1;
        for (int i = tid; i < 32 * 64; i += 256) {
            int r = i >> 6, ch = i & 63;
            cpa16(cvsm(&Hsm[r][ch * 8]), &g_hencbf[dir][rd][r * 512 + ch * 8]);
        }
        asm volatile("cp.async.commit_group;");
        asm volatile("cp.async.wait_group 0;");
        __syncthreads();
        if (grp < 3) {
            float accA[4] = {0.f, 0.f, 0.f, 0.f};
            float accB[4] = {0.f, 0.f, 0.f, 0.f};
#pragma unroll 4
            for (int ks = 0; ks < 16; ks++) {
                uint32_t a4[4], b2[2], a4b[4], b2b[2];
                ldm_x4(a4, cvsm(&Hsm[16 * wm + (lane & 15)][ks * 16 + ((lane & 16) ? 8 : 0)]));
                ldm_x2(b2, cvsm(&Wsm[grp * 8 + (lane & 7)][ks * 16 + ((lane & 8) ? 8 : 0)]));
                mma16816(accA, a4, b2);
                ldm_x4(a4b, cvsm(&Hsm[16 * wm + (lane & 15)][(ks + 16) * 16 + ((lane & 16) ? 8 : 0)]));
                ldm_x2(b2b, cvsm(&Wsm[grp * 8 + (lane & 7)][(ks + 16) * 16 + ((lane & 8) ? 8 : 0)]));
                mma16816(accB, a4b, b2b);
            }
            int r0 = wm * 16 + (lane >> 2);
            int c0 = (lane & 3) * 2;
            gh_sm[grp][r0][c0] = accA[0] + accB[0];
            gh_sm[grp][r0][c0 + 1] = accA[1] + accB[1];
            gh_sm[grp][r0 + 8][c0] = accA[2] + accB[2];
            gh_sm[grp][r0 + 8][c0 + 1] = accA[3] + accB[3];
        }
        __syncthreads();
        {
            int b = tid >> 3, jj = tid & 7;
            int j = jt * 8 + jj;
            int tf = dir ? (63 - t) : t;
            bool m = tf < slen[b];
            int base = (b * 64 + tf) * 1536;
            float ghr = gh_sm[0][b][jj] + bhh[j];
            float ghz = gh_sm[1][b][jj] + bhh[512 + j];
            float ghn = gh_sm[2][b][jj] + bhh[1024 + j];
            float h = g_henc[dir][rd][b * 512 + j];
            float r = sigf(gx[base + j] + ghr);
            float z = sigf(gx[base + 512 + j] + ghz);
            float n = tanhf(gx[base + 1024 + j] + r * ghn);
            float hn = (1.f - z) * n + z * h;
            float hout = m ? hn : h;
            g_henc[dir][wr][b * 512 + j] = hout;
            g_hencbf[dir][wr][b * 512 + j] = __float2bfloat16(hout);
            g_srchidbf[(b * 64 + tf) * 1024 + dir * 512 + j] = __float2bfloat16(m ? hn : 0.f);
        }
        sem_arrive_block(&g_semE);
        sem_wait_block(&g_semE, 128u * (t + 1));
    }
}

// -------------------- persistent decoder: 96 blocks, split semaphores, ILP-2 --------------------
__global__ __launch_bounds__(256) void dec_persist(const float* __restrict__ Ab,
                                                   const float* __restrict__ Av,
                                                   const float* __restrict__ dbhh,
                                                   const int* __restrict__ slen,
                                                   const int* __restrict__ tlen) {
    extern __shared__ char smem[];
    int bid = blockIdx.x, tid = threadIdx.x, lane = tid & 31, w = tid >> 5;

    if (bid < 32) {
        int b = bid;
        bf16 (*Uhc)[520] = (bf16(*)[520])smem;                          // 64 rows
        bf16 (*SHc)[1048] = (bf16(*)[1048])(smem + 64 * 520 * 2);       // 64 rows
        float* a_sm = (float*)(smem + 64 * 520 * 2 + 64 * 1048 * 2);    // 512
        float* wts = a_sm + 512;                                        // 64
        float* Ab_sm = wts + 64;                                        // 512
        float* Av_sm = Ab_sm + 512;                                     // 512
        for (int i = tid; i < 64 * 64; i += 256) {
            int s = i >> 6, ch = i & 63;
            *(uint4*)&Uhc[s][ch * 8] = *(const uint4*)&g_Uhbf[(b * 64 + s) * 512 + ch * 8];
        }
        for (int i = tid; i < 64 * 128; i += 256) {
            int s = i >> 7, ch = i & 127;
            *(uint4*)&SHc[s][ch * 8] = *(const uint4*)&g_srchidbf[(b * 64 + s) * 1024 + ch * 8];
        }
        for (int j = tid; j < 512; j += 256) { Ab_sm[j] = Ab[j]; Av_sm[j] = Av[j]; }
        int L = slen[b];
        for (int t = 0; t < T_; t++) {
            sem_wait_block(&g_semA, 64u * (t + 1));
            for (int j = tid; j < 512; j += 256) a_sm[j] = g_a[b * 512 + j] + Ab_sm[j];
            __syncthreads();
#pragma unroll
            for (int si = 0; si < 8; si++) {
                int s = w * 8 + si;
                float p = 0.f;
#pragma unroll 4
                for (int j2 = lane; j2 < 256; j2 += 32) {
                    int j = j2 * 2;
                    float2 uv = __bfloat1622float2(*(const __nv_bfloat162*)&Uhc[s][j]);
                    p += Av_sm[j] * tanha(uv.x + a_sm[j]);
                    p += Av_sm[j + 1] * tanha(uv.y + a_sm[j + 1]);
                }
#pragma unroll
                for (int o = 16; o > 0; o >>= 1) p += __shfl_xor_sync(0xffffffffu, p, o);
                if (lane == 0) wts[s] = (s < L) ? p : p - 1e9f;
            }
            __syncthreads();
            if (w == 0) {
                float e0 = wts[lane], e1 = wts[lane + 32];
                float m = fmaxf(e0, e1);
#pragma unroll
                for (int o = 16; o > 0; o >>= 1) m = fmaxf(m, __shfl_xor_sync(0xffffffffu, m, o));
                float x0 = __expf(e0 - m), x1 = __expf(e1 - m);
                float sm = x0 + x1;
#pragma unroll
                for (int o = 16; o > 0; o >>= 1) sm += __shfl_xor_sync(0xffffffffu, sm, o);
                float inv = 1.f / sm;
                wts[lane] = x0 * inv;
                wts[lane + 32] = x1 * inv;
            }
            __syncthreads();
            for (int j = tid; j < 1024; j += 256) {
                float c0 = 0.f, c1 = 0.f;
#pragma unroll 16
                for (int s = 0; s < 64; s += 2) {
                    c0 += wts[s] * __bfloat162float(SHc[s][j]);
                    c1 += wts[s + 1] * __bfloat162float(SHc[s + 1][j]);
                }
                g_cbf[b * 1024 + j] = __float2bfloat16(c0 + c1);
            }
            sem_arrive_block(&g_semB);
        }
    } else {
        int gid = bid - 32;
        bf16 (*Wih)[1032] = (bf16(*)[1032])smem;                                  // 24 rows (ctx)
        bf16 (*Whh)[520] = (bf16(*)[520])(smem + 24 * 1032 * 2);                  // 24 rows
        bf16 (*AWc)[520] = (bf16(*)[520])(smem + 24 * 1032 * 2 + 24 * 520 * 2);   // 8 rows
        bf16 (*Asm)[1048] = (bf16(*)[1048])(smem + 24 * 1032 * 2 + 32 * 520 * 2); // 32 rows
        float (*gh_sm)[32][8] = (float(*)[32][8])(smem + 24 * 1032 * 2 + 32 * 520 * 2 + 32 * 1048 * 2);
        float (*gx_sm)[32][8] = (float(*)[32][8])((char*)gh_sm + 3 * 32 * 8 * 4);
        for (int i = tid; i < 24 * 128; i += 256) {
            int r = i >> 7, ch = i & 127;
            int grow = (r >> 3) * 512 + gid * 8 + (r & 7);
            *(uint4*)&Wih[r][ch * 8] = *(const uint4*)&g_dWih_bf[grow * 1536 + 512 + ch * 8];
        }
        for (int i = tid; i < 24 * 64; i += 256) {
            int r = i >> 6, ch = i & 63;
            int grow = (r >> 3) * 512 + gid * 8 + (r & 7);
            *(uint4*)&Whh[r][ch * 8] = *(const uint4*)&g_dWhh_bf[grow * 512 + ch * 8];
        }
        for (int i = tid; i < 8 * 64; i += 256) {
            int r = i >> 6, ch = i & 63;
            *(uint4*)&AWc[r][ch * 8] = *(const uint4*)&g_AW_bf[(gid * 8 + r) * 512 + ch * 8];
        }
        int wm = w & 1, grp = w >> 1;    // 8 warps: 2 m-tiles x {a, r, z, n}
        for (int t = 0; t < T_; t++) {
            // ---- stage A: load h; grp0 -> a (early signal); grp1..3 -> gh (overlaps attn) ----
            for (int i = tid; i < 32 * 64; i += 256) {
                int r = i >> 6, ch = i & 63;
                cpa16(cvsm(&Asm[r][ch * 8]), &g_hdecbf[r * 512 + ch * 8]);
            }
            asm volatile("cp.async.commit_group;");
            asm volatile("cp.async.wait_group 0;");
            __syncthreads();
            if (grp == 0) {
                float accA[4] = {0.f, 0.f, 0.f, 0.f};
                float accB[4] = {0.f, 0.f, 0.f, 0.f};
#pragma unroll 4
                for (int ks = 0; ks < 16; ks++) {
                    uint32_t a4[4], b2[2], a4b[4], b2b[2];
                    ldm_x4(a4, cvsm(&Asm[16 * wm + (lane & 15)][ks * 16 + ((lane & 16) ? 8 : 0)]));
                    ldm_x2(b2, cvsm(&AWc[(lane & 7)][ks * 16 + ((lane & 8) ? 8 : 0)]));
                    mma16816(accA, a4, b2);
                    ldm_x4(a4b, cvsm(&Asm[16 * wm + (lane & 15)][(ks + 16) * 16 + ((lane & 16) ? 8 : 0)]));
                    ldm_x2(b2b, cvsm(&AWc[(lane & 7)][(ks + 16) * 16 + ((lane & 8) ? 8 : 0)]));
                    mma16816(accB, a4b, b2b);
                }
                int r0 = wm * 16 + (lane >> 2);
                int c0 = gid * 8 + (lane & 3) * 2;
                g_a[r0 * 512 + c0] = accA[0] + accB[0];
                g_a[r0 * 512 + c0 + 1] = accA[1] + accB[1];
                g_a[(r0 + 8) * 512 + c0] = accA[2] + accB[2];
                g_a[(r0 + 8) * 512 + c0 + 1] = accA[3] + accB[3];
                __threadfence();
                asm volatile("bar.sync 1, 64;" ::: "memory");
                if (tid == 0) sem_signal(&g_semA);       // attention may start
            } else {
                int g = grp - 1;
                float accA[4] = {0.f, 0.f, 0.f, 0.f};
                float accB[4] = {0.f, 0.f, 0.f, 0.f};
#pragma unroll 4
                for (int ks = 0; ks < 16; ks++) {
                    uint32_t a4[4], b2[2], a4b[4], b2b[2];
                    ldm_x4(a4, cvsm(&Asm[16 * wm + (lane & 15)][ks * 16 + ((lane & 16) ? 8 : 0)]));
                    ldm_x2(b2, cvsm(&Whh[g * 8 + (lane & 7)][ks * 16 + ((lane & 8) ? 8 : 0)]));
                    mma16816(accA, a4, b2);
                    ldm_x4(a4b, cvsm(&Asm[16 * wm + (lane & 15)][(ks + 16) * 16 + ((lane & 16) ? 8 : 0)]));
                    ldm_x2(b2b, cvsm(&Whh[g * 8 + (lane & 7)][(ks + 16) * 16 + ((lane & 8) ? 8 : 0)]));
                    mma16816(accB, a4b, b2b);
                }
                int r0 = wm * 16 + (lane >> 2);
                int c0 = (lane & 3) * 2;
                gh_sm[g][r0][c0] = accA[0] + accB[0];
                gh_sm[g][r0][c0 + 1] = accA[1] + accB[1];
                gh_sm[g][r0 + 8][c0] = accA[2] + accB[2];
                gh_sm[g][r0 + 8][c0 + 1] = accA[3] + accB[3];
            }
            // ---- wait for context ----
            sem_wait_block(&g_semB, 32u * (t + 1));
            for (int i = tid; i < 32 * 128; i += 256) {
                int r = i >> 7, ch = i & 127;
                cpa16(cvsm(&Asm[r][ch * 8]), &g_cbf[r * 1024 + ch * 8]);
            }
            asm volatile("cp.async.commit_group;");
            asm volatile("cp.async.wait_group 0;");
            __syncthreads();
            if (grp >= 1) {
                int g = grp - 1;
                float accA[4] = {0.f, 0.f, 0.f, 0.f};
                float accB[4] = {0.f, 0.f, 0.f, 0.f};
#pragma unroll 4
                for (int ks = 0; ks < 32; ks++) {
                    uint32_t a4[4], b2[2], a4b[4], b2b[2];
                    ldm_x4(a4, cvsm(&Asm[16 * wm + (lane & 15)][ks * 16 + ((lane & 16) ? 8 : 0)]));
                    ldm_x2(b2, cvsm(&Wih[g * 8 + (lane & 7)][ks * 16 + ((lane & 8) ? 8 : 0)]));
                    mma16816(accA, a4, b2);
                    ldm_x4(a4b, cvsm(&Asm[16 * wm + (lane & 15)][(ks + 32) * 16 + ((lane & 16) ? 8 : 0)]));
                    ldm_x2(b2b, cvsm(&Wih[g * 8 + (lane & 7)][(ks + 32) * 16 + ((lane & 8) ? 8 : 0)]));
                    mma16816(accB, a4b, b2b);
                }
                int r0 = wm * 16 + (lane >> 2);
                int c0 = (lane & 3) * 2;
                gx_sm[g][r0][c0] = accA[0] + accB[0];
                gx_sm[g][r0][c0 + 1] = accA[1] + accB[1];
                gx_sm[g][r0 + 8][c0] = accA[2] + accB[2];
                gx_sm[g][r0 + 8][c0 + 1] = accA[3] + accB[3];
            }
            __syncthreads();
            // ---- pointwise: 256 threads, one (b, j) element each ----
            {
                int b = tid >> 3, jj = tid & 7;
                int j = gid * 8 + jj;
                bool m = t < tlen[b];
                const float* ge = g_gxemb + (b * 64 + t) * 1536;
                float gxr = gx_sm[0][b][jj] + ge[j];
                float gxz = gx_sm[1][b][jj] + ge[512 + j];
                float gxn = gx_sm[2][b][jj] + ge[1024 + j];
                float ghr = gh_sm[0][b][jj] + dbhh[j];
                float ghz = gh_sm[1][b][jj] + dbhh[512 + j];
                float ghn = gh_sm[2][b][jj] + dbhh[1024 + j];
                float h = g_hdec[b * 512 + j];
                float r = sigf(gxr + ghr);
                float z = sigf(gxz + ghz);
                float n = tanhf(gxn + r * ghn);
                float hn = (1.f - z) * n + z * h;
                float hout = m ? hn : h;
                g_hdec[b * 512 + j] = hout;
                g_hdecbf[b * 512 + j] = __float2bfloat16(hout);
                g_decbf[(b * 64 + t) * 512 + j] = __float2bfloat16(m ? hn : 0.f);
            }
            sem_arrive_block(&g_semC);
            sem_wait_block(&g_semC, 64u * (t + 1));      // gemm-group barrier on h
        }
    }
}

// -------------------- logits GEMM (cp.async 2-stage) + exp-sum + pick --------------------
__global__ __launch_bounds__(256) void logits_mma(const float* __restrict__ bias,
                                                  const int* __restrict__ tseq) {
    __shared__ bf16 As[2][128][40];
    __shared__ bf16 Bs[2][128][40];
    __shared__ float rowsum[128][2];
    int tid = threadIdx.x, lane = tid & 31, wid = tid >> 5;
    int wm = wid & 3, wn = wid >> 2;
    int row0 = blockIdx.y * 128, col0 = blockIdx.x * 128;
    int r = tid >> 2, c = tid & 3;
    float acc[2][8][4];
#pragma unroll
    for (int mt = 0; mt < 2; mt++)
#pragma unroll
        for (int nt = 0; nt < 8; nt++)
#pragma unroll
            for (int cc = 0; cc < 4; cc++) acc[mt][nt][cc] = 0.f;

#define ISSUE(kt, st)                                                                  \
    do {                                                                               \
        int k0_ = (kt) * 32;                                                           \
        cpa16(cvsm(&As[st][r][c * 8]), &g_decbf[(row0 + r) * 512 + k0_ + c * 8]);      \
        cpa16(cvsm(&As[st][r + 64][c * 8]), &g_decbf[(row0 + r + 64) * 512 + k0_ + c * 8]); \
        cpa16(cvsm(&Bs[st][r][c * 8]), &g_Wbf[(col0 + r) * 512 + k0_ + c * 8]);        \
        cpa16(cvsm(&Bs[st][r + 64][c * 8]), &g_Wbf[(col0 + r + 64) * 512 + k0_ + c * 8]); \
        asm volatile("cp.async.commit_group;");                                        \
    } while (0)

    ISSUE(0, 0);
    for (int kt = 0; kt < 16; kt++) {
        int st = kt & 1;
        if (kt < 15) {
            ISSUE(kt + 1, st ^ 1);
            asm volatile("cp.async.wait_group 1;");
        } else {
            asm volatile("cp.async.wait_group 0;");
        }
        __syncthreads();
#pragma unroll
        for (int kk = 0; kk < 2; kk++) {
            int kb = kk * 16;
            uint32_t af[2][4];
#pragma unroll
            for (int mt = 0; mt < 2; mt++)
                ldm_x4(af[mt], cvsm(&As[st][wm * 32 + mt * 16 + (lane & 15)][kb + ((lane & 16) ? 8 : 0)]));
            uint32_t bfr[8][2];
#pragma unroll
            for (int np = 0; np < 4; np++) {
                uint32_t t4[4];
                ldm_x4(t4, cvsm(&Bs[st][wn * 64 + np * 16 + (lane & 7) + ((lane & 16) ? 8 : 0)][kb + ((lane & 8) ? 8 : 0)]));
                bfr[np * 2][0] = t4[0]; bfr[np * 2][1] = t4[1];
                bfr[np * 2 + 1][0] = t4[2]; bfr[np * 2 + 1][1] = t4[3];
            }
#pragma unroll
            for (int mt = 0; mt < 2; mt++)
#pragma unroll
                for (int nt = 0; nt < 8; nt++)
                    mma16816(acc[mt][nt], af[mt], bfr[nt]);
        }
        __syncthreads();
    }
#undef ISSUE

    float sums[2][2] = {{0.f, 0.f}, {0.f, 0.f}};
    int gl[2][2];
#pragma unroll
    for (int mt = 0; mt < 2; mt++)
#pragma unroll
        for (int h = 0; h < 2; h++) {
            int row = row0 + wm * 32 + mt * 16 + (lane >> 2) + h * 8;
            int tt = row & 63;
            gl[mt][h] = (tt < T_ - 1) ? tseq[(row >> 6) * T_ + tt + 1] : 0;
        }
#pragma unroll
    for (int mt = 0; mt < 2; mt++)
#pragma unroll
        for (int nt = 0; nt < 8; nt++) {
            int cb = col0 + wn * 64 + nt * 8 + (lane & 3) * 2;
            float b0 = bias[cb], b1 = bias[cb + 1];
#pragma unroll
            for (int h = 0; h < 2; h++) {
                float v0 = acc[mt][nt][h * 2] + b0;
                float v1 = acc[mt][nt][h * 2 + 1] + b1;
                sums[mt][h] += __expf(v0) + __expf(v1);
                int row = row0 + wm * 32 + mt * 16 + (lane >> 2) + h * 8;
                if (cb == gl[mt][h]) g_picked[row] = v0;
                if (cb + 1 == gl[mt][h]) g_picked[row] = v1;
            }
        }
#pragma unroll
    for (int mt = 0; mt < 2; mt++)
#pragma unroll
        for (int h = 0; h < 2; h++) {
            float s = sums[mt][h];
            s += __shfl_xor_sync(0xffffffffu, s, 1);
            s += __shfl_xor_sync(0xffffffffu, s, 2);
            if ((lane & 3) == 0)
                rowsum[wm * 32 + mt * 16 + (lane >> 2) + h * 8][wn] = s;
        }
    __syncthreads();
    if (tid < 128)
        g_partial[(row0 + tid) * NVT + blockIdx.x] = rowsum[tid][0] + rowsum[tid][1];
}

// -------------------- per-row lse + nll (warp per row) --------------------
__global__ void rowloss_kernel(const int* __restrict__ tseq) {
    int lane = threadIdx.x & 31;
    int r = blockIdx.x * 8 + (threadIdx.x >> 5);
    float s = 0.f;
    for (int v = lane; v < NVT; v += 32) s += g_partial[r * NVT + v];
#pragma unroll
    for (int o = 16; o > 0; o >>= 1) s += __shfl_xor_sync(0xffffffffu, s, o);
    if (lane == 0) {
        int b = r >> 6, t = r & 63;
        int g = (t < T_ - 1) ? tseq[b * T_ + t + 1] : 0;
        if (g != 0) { g_rowloss[r] = logf(s) - g_picked[r]; g_rowvalid[r] = 1.f; }
        else        { g_rowloss[r] = 0.f;                   g_rowvalid[r] = 0.f; }
    }
}

__global__ void final_kernel(float* __restrict__ out) {
    int tid = threadIdx.x;
    float s = 0.f, c = 0.f;
    for (int r = tid; r < ROWS; r += 256) { s += g_rowloss[r]; c += g_rowvalid[r]; }
#pragma unroll
    for (int o = 16; o > 0; o >>= 1) {
        s += __shfl_xor_sync(0xffffffffu, s, o);
        c += __shfl_xor_sync(0xffffffffu, c, o);
    }
    __shared__ float ws[8], wc[8];
    if ((tid & 31) == 0) { ws[tid >> 5] = s; wc[tid >> 5] = c; }
    __syncthreads();
    if (tid == 0) {
        float S = 0.f, C = 0.f;
        for (int i = 0; i < 8; i++) { S += ws[i]; C += wc[i]; }
        out[0] = S / C;
    }
}

// -------------------- launch --------------------
extern "C" void kernel_launch(void* const* d_in, const int* in_sizes, int n_in,
                              void* d_out, int out_size) {
    const int*   src_seqs = (const int*)d_in[0];
    const int*   src_len  = (const int*)d_in[1];
    const int*   tgt_seqs = (const int*)d_in[2];
    const int*   tgt_len  = (const int*)d_in[3];
    const float* src_emb  = (const float*)d_in[4];
    const float* eWih_f   = (const float*)d_in[5];
    const float* eWhh_f   = (const float*)d_in[6];
    const float* ebih_f   = (const float*)d_in[7];
    const float* ebhh_f   = (const float*)d_in[8];
    const float* eWih_b   = (const float*)d_in[9];
    const float* eWhh_b   = (const float*)d_in[10];
    const float* ebih_b   = (const float*)d_in[11];
    const float* ebhh_b   = (const float*)d_in[12];
    const float* tgt_emb  = (const float*)d_in[13];
    const float* dWih     = (const float*)d_in[14];
    const float* dWhh     = (const float*)d_in[15];
    const float* dbih     = (const float*)d_in[16];
    const float* dbhh     = (const float*)d_in[17];
    const float* U_w      = (const float*)d_in[18];
    const float* U_b      = (const float*)d_in[19];
    const float* A_W      = (const float*)d_in[20];
    const float* A_b      = (const float*)d_in[21];
    const float* A_v      = (const float*)d_in[22];
    const float* out_w    = (const float*)d_in[23];
    const float* out_b    = (const float*)d_in[24];

    cudaFuncSetAttribute(enc_persist, cudaFuncAttributeMaxDynamicSharedMemorySize, 61312);
    cudaFuncSetAttribute(dec_persist, cudaFuncAttributeMaxDynamicSharedMemorySize, 207104);

    init_states<<<64, 256>>>();
    embed_all<<<8192, 256>>>(src_seqs, src_emb, tgt_seqs, tgt_emb);
    conv_all<<<22912, 256>>>(eWih_f, eWih_b, eWhh_f, eWhh_b, U_w, A_W, dWih, dWhh, out_w);

    // all three input-gate GEMMs in one launch
    gx_all<<<dim3(12, 16, 3), 256>>>(ebih_f, ebih_b, dbih);

    enc_persist<<<128, 256, 61312>>>(ebhh_f, ebhh_b, src_len);

    uh_gemm<<<dim3(4, 16), 256>>>(U_b);

    dec_persist<<<96, 256, 207104>>>(A_b, A_v, dbhh, src_len, tgt_len);

    logits_mma<<<dim3(NVT, 16), 256>>>(out_b, tgt_seqs);
    rowloss_kernel<<<256, 256>>>(tgt_seqs);
    final_kernel<<<1, 256>>>((float*)d_out);
}